// round 10
// baseline (speedup 1.0000x reference)
#include <cuda_runtime.h>

#define NQ 12
#define DIM 4096
#define NLAYERS 3
#define NGATES (NLAYERS * NQ)   // 36
#define TPB 512
#define RPT 8                   // register amplitudes per thread per pack
#define STRIDE 9                // padded smem row stride (in 8-byte units)
#define BUF (TPB * STRIDE)      // 4608 u64 per component per pack

typedef unsigned long long u64;

// Pre-packed gate coefficients: 36 gates x 12 float2 (duplicated / negated-duplicated)
__device__ float2 g_gates2[NGATES * 12];

// ---------------- f32x2 helpers (sm_103a packed fp32) ----------------
__device__ __forceinline__ u64 pk2(float x, float y) {
    u64 r; asm("mov.b64 %0, {%1, %2};" : "=l"(r) : "f"(x), "f"(y)); return r;
}
__device__ __forceinline__ void unpk2(u64 a, float& x, float& y) {
    asm("mov.b64 {%0, %1}, %2;" : "=f"(x), "=f"(y) : "l"(a));
}
__device__ __forceinline__ u64 f2fma(u64 a, u64 b, u64 c) {
    u64 d; asm("fma.rn.f32x2 %0, %1, %2, %3;" : "=l"(d) : "l"(a), "l"(b), "l"(c)); return d;
}
__device__ __forceinline__ u64 f2mul(u64 a, u64 b) {
    u64 d; asm("mul.rn.f32x2 %0, %1, %2;" : "=l"(d) : "l"(a), "l"(b)); return d;
}
__device__ __forceinline__ u64 f2add(u64 a, u64 b) {
    u64 d; asm("add.rn.f32x2 %0, %1, %2;" : "=l"(d) : "l"(a), "l"(b)); return d;
}
__device__ __forceinline__ void bar64(int id) {
    asm volatile("bar.sync %0, 64;" :: "r"(id) : "memory");
}

// ---------------------------------------------------------------------------
// Prep: fuse RZ*RY*RX per gate; emit 12 duplicated-packed coefficient pairs.
// ---------------------------------------------------------------------------
__global__ void prep_gates(const float* __restrict__ params) {
    int g = blockIdx.x * blockDim.x + threadIdx.x;
    if (g >= NGATES) return;
    float a = params[3 * g + 0] * 0.5f;
    float b = params[3 * g + 1] * 0.5f;
    float c = params[3 * g + 2] * 0.5f;
    float ca = cosf(a), sa = sinf(a);
    float cb = cosf(b), sb = sinf(b);
    float cc = cosf(c), sc = sinf(c);
    float m00r = cb * ca, m00i = sb * sa;
    float m01r = -sb * ca, m01i = -cb * sa;
    float m10r = sb * ca, m10i = -cb * sa;
    float m11r = cb * ca, m11i = -sb * sa;
    float u00r = cc * m00r + sc * m00i, u00i = cc * m00i - sc * m00r;
    float u01r = cc * m01r + sc * m01i, u01i = cc * m01i - sc * m01r;
    float u10r = cc * m10r - sc * m10i, u10i = cc * m10i + sc * m10r;
    float u11r = cc * m11r - sc * m11i, u11i = cc * m11i + sc * m11r;
    float2* o = &g_gates2[g * 12];
    o[0]  = make_float2(u00r, u00r);
    o[1]  = make_float2(-u00i, -u00i);
    o[2]  = make_float2(u01r, u01r);
    o[3]  = make_float2(-u01i, -u01i);
    o[4]  = make_float2(u00i, u00i);
    o[5]  = make_float2(u01i, u01i);
    o[6]  = make_float2(u10r, u10r);
    o[7]  = make_float2(-u10i, -u10i);
    o[8]  = make_float2(u11r, u11r);
    o[9]  = make_float2(-u11i, -u11i);
    o[10] = make_float2(u10i, u10i);
    o[11] = make_float2(u11i, u11i);
}

// 3 gates on the register-index bits for BOTH packs (coeff regs shared).
__device__ __forceinline__ void apply3_dual(
    u64 v0re[RPT], u64 v0im[RPT], u64 v1re[RPT], u64 v1im[RPT],
    const u64* __restrict__ sG2, int gbase) {
#pragma unroll
    for (int qq = 0; qq < 3; qq++) {
        const u64* C = &sG2[(gbase + qq) * 12];
        const u64 c0 = C[0], c1 = C[1], c2 = C[2], c3 = C[3], c4 = C[4], c5 = C[5];
        const u64 c6 = C[6], c7 = C[7], c8 = C[8], c9 = C[9], c10 = C[10], c11 = C[11];
        const int mb = 4 >> qq;
#pragma unroll
        for (int r = 0; r < RPT; r++) {
            if (!(r & mb)) {
                const int r1 = r | mb;
                {
                    u64 a0re = v0re[r],  a0im = v0im[r];
                    u64 a1re = v0re[r1], a1im = v0im[r1];
                    v0re[r]  = f2fma(c0, a0re, f2fma(c1, a0im, f2fma(c2, a1re, f2mul(c3, a1im))));
                    v0im[r]  = f2fma(c4, a0re, f2fma(c0, a0im, f2fma(c5, a1re, f2mul(c2, a1im))));
                    v0re[r1] = f2fma(c6, a0re, f2fma(c7, a0im, f2fma(c8, a1re, f2mul(c9, a1im))));
                    v0im[r1] = f2fma(c10, a0re, f2fma(c6, a0im, f2fma(c11, a1re, f2mul(c8, a1im))));
                }
                {
                    u64 a0re = v1re[r],  a0im = v1im[r];
                    u64 a1re = v1re[r1], a1im = v1im[r1];
                    v1re[r]  = f2fma(c0, a0re, f2fma(c1, a0im, f2fma(c2, a1re, f2mul(c3, a1im))));
                    v1im[r]  = f2fma(c4, a0re, f2fma(c0, a0im, f2fma(c5, a1re, f2mul(c2, a1im))));
                    v1re[r1] = f2fma(c6, a0re, f2fma(c7, a0im, f2fma(c8, a1re, f2mul(c9, a1im))));
                    v1im[r1] = f2fma(c10, a0re, f2fma(c6, a0im, f2fma(c11, a1re, f2mul(c8, a1im))));
                }
            }
        }
    }
}

// ---------------------------------------------------------------------------
// One CTA per 4 BATCH ELEMENTS: two u64-packed states per thread.
// Layouts: L0 r={b11,b10,b9} | L1 r={b8,b7,b6} | L2 r={b5,b4,b3} | L3 r={b2,b1,b0}
// All exchanges share one smem region per pack-component (147KB total).
// Race-minimal sync scopes (verified pairwise):
//   pre-X1 full | post-X1 full | pre/post-X2 bar64 | pre/post-X3 syncwarp |
//   X4: stores own rows (no pre-sync) | post-X4 full.
// ---------------------------------------------------------------------------
extern __shared__ __align__(16) u64 dynsm[];

__global__ __launch_bounds__(TPB, 1) void qsim_kernel(
    const float* __restrict__ x, float* __restrict__ out) {
    __shared__ u64 sG2[NGATES * 12];
    __shared__ u64 sRed[2 * (TPB / 32)];
    __shared__ float sAcc[4 * NQ];

    u64* b0Re = dynsm;
    u64* b0Im = dynsm + BUF;
    u64* b1Re = dynsm + 2 * BUF;
    u64* b1Im = dynsm + 3 * BUF;

    const int tid = threadIdx.x;
    const int bid = blockIdx.x;
    const float* xb0 = x + (size_t)(4 * bid) * DIM;
    const float* xb1 = xb0 + DIM;
    const float* xb2 = xb0 + 2 * DIM;
    const float* xb3 = xb0 + 3 * DIM;

    if (tid < NGATES * 12) sG2[tid] = ((const u64*)g_gates2)[tid];
    if (tid < 4 * NQ) sAcc[tid] = 0.0f;

    // ---- load 4 elements as 2 packs (L0) + per-element sums of squares ----
    u64 v0re[RPT], v0im[RPT], v1re[RPT], v1im[RPT];
    u64 ss0 = 0, ss1 = 0;
#pragma unroll
    for (int r = 0; r < RPT; r++) {
        int i = (r << 9) | tid;
        u64 va = pk2(xb0[i], xb1[i]);
        u64 vb = pk2(xb2[i], xb3[i]);
        v0re[r] = va; v0im[r] = 0;
        v1re[r] = vb; v1im[r] = 0;
        ss0 = f2fma(va, va, ss0);
        ss1 = f2fma(vb, vb, ss1);
    }
#pragma unroll
    for (int o = 16; o; o >>= 1) {
        ss0 = f2add(ss0, __shfl_xor_sync(0xffffffffu, ss0, o));
        ss1 = f2add(ss1, __shfl_xor_sync(0xffffffffu, ss1, o));
    }
    if ((tid & 31) == 0) {
        sRed[tid >> 5] = ss0;
        sRed[(TPB / 32) + (tid >> 5)] = ss1;
    }
    __syncthreads();
    ss0 = 0; ss1 = 0;
#pragma unroll
    for (int w = 0; w < TPB / 32; w++) {
        ss0 = f2add(ss0, sRed[w]);
        ss1 = f2add(ss1, sRed[(TPB / 32) + w]);
    }
    float sa0, sa1, sb0, sb1;
    unpk2(ss0, sa0, sa1); unpk2(ss1, sb0, sb1);
    const u64 inv0 = pk2(rsqrtf(sa0), rsqrtf(sa1));
    const u64 inv1 = pk2(rsqrtf(sb0), rsqrtf(sb1));
#pragma unroll
    for (int r = 0; r < RPT; r++) {
        v0re[r] = f2mul(v0re[r], inv0);
        v1re[r] = f2mul(v1re[r], inv1);
    }

    // exchange write bases (u64 units)
    const int base1 = (tid & 63) * STRIDE + ((tid >> 6) & 7);                      // +r*576
    const int base2 = (((tid >> 6) << 6) | (tid & 7)) * STRIDE + ((tid >> 3) & 7); // +r*72
    const int base3 = (tid >> 3) * (8 * STRIDE) + (tid & 7);                       // +r*9
    const int baseR = tid * STRIDE;                                                // canonical rows
    const int mybar = 1 + (tid >> 6);                                              // named barrier ids 1..8
    // sigma(t): XOR-linear CNOT-ring permutation (verified)
    const int sig_t = ((tid ^ (tid >> 1)) & 0x0FF) | (tid & 0x100)
                    | ((tid & 1) ? 0xC00 : 0);

    // ---- circuit ----
#pragma unroll 1
    for (int layer = 0; layer < NLAYERS; layer++) {
        const int gbase = layer * NQ;

        apply3_dual(v0re, v0im, v1re, v1im, sG2, gbase + 0);   // bits 11,10,9
        __syncthreads();                                        // prior sigma-readers done
#pragma unroll
        for (int r = 0; r < RPT; r++) {                         // X1 stores (global scatter)
            int a = base1 + r * (64 * STRIDE);
            b0Re[a] = v0re[r]; b0Im[a] = v0im[r];
            b1Re[a] = v1re[r]; b1Im[a] = v1im[r];
        }
        __syncthreads();
#pragma unroll
        for (int r = 0; r < RPT; r++) {
            int a = baseR + r;
            v0re[r] = b0Re[a]; v0im[r] = b0Im[a];
            v1re[r] = b1Re[a]; v1im[r] = b1Im[a];
        }

        apply3_dual(v0re, v0im, v1re, v1im, sG2, gbase + 3);   // bits 8,7,6
        bar64(mybar);                                           // prior X1-readers in 64-group done
#pragma unroll
        for (int r = 0; r < RPT; r++) {                         // X2 stores (64-group rows)
            int a = base2 + r * (8 * STRIDE);
            b0Re[a] = v0re[r]; b0Im[a] = v0im[r];
            b1Re[a] = v1re[r]; b1Im[a] = v1im[r];
        }
        bar64(mybar);
#pragma unroll
        for (int r = 0; r < RPT; r++) {
            int a = baseR + r;
            v0re[r] = b0Re[a]; v0im[r] = b0Im[a];
            v1re[r] = b1Re[a]; v1im[r] = b1Im[a];
        }

        apply3_dual(v0re, v0im, v1re, v1im, sG2, gbase + 6);   // bits 5,4,3
        __syncwarp();                                           // prior X2-readers in 8-group done
#pragma unroll
        for (int r = 0; r < RPT; r++) {                         // X3 stores (8-group rows)
            int a = base3 + r * STRIDE;
            b0Re[a] = v0re[r]; b0Im[a] = v0im[r];
            b1Re[a] = v1re[r]; b1Im[a] = v1im[r];
        }
        __syncwarp();
#pragma unroll
        for (int r = 0; r < RPT; r++) {
            int a = baseR + r;
            v0re[r] = b0Re[a]; v0im[r] = b0Im[a];
            v1re[r] = b1Re[a]; v1im[r] = b1Im[a];
        }

        apply3_dual(v0re, v0im, v1re, v1im, sG2, gbase + 9);   // bits 2,1,0
#pragma unroll
        for (int r = 0; r < RPT; r++) {                         // X4 stores own rows (race-free)
            int a = baseR + r;
            b0Re[a] = v0re[r]; b0Im[a] = v0im[r];
            b1Re[a] = v1re[r]; b1Im[a] = v1im[r];
        }
        __syncthreads();
        {
            // gather to L0 with CNOT-ring sigma folded in (verified constants)
            const int SIGC[RPT] = {0x000, 0x300, 0x600, 0x500,
                                   0xC00, 0xF00, 0xA00, 0x900};
#pragma unroll
            for (int r = 0; r < RPT; r++) {
                int j = SIGC[r] ^ sig_t;
                int a = j + (j >> 3);              // == (j>>3)*9 + (j&7)
                v0re[r] = b0Re[a]; v0im[r] = b0Im[a];
                v1re[r] = b1Re[a]; v1im[r] = b1Im[a];
            }
        }
    }

    // ---- expectations <Z_q>, pack-sequential to limit register pressure ----
#pragma unroll 1
    for (int pk = 0; pk < 2; pk++) {
        u64 acc[NQ];
#pragma unroll
        for (int q = 0; q < NQ; q++) acc[q] = 0;
#pragma unroll
        for (int r = 0; r < RPT; r++) {
            u64 re = pk ? v1re[r] : v0re[r];
            u64 im = pk ? v1im[r] : v0im[r];
            u64 p2 = f2fma(re, re, f2mul(im, im));
            u64 pn = p2 ^ 0x8000000080000000ULL;   // exact negation of both halves
            const int i = (r << 9) | tid;
#pragma unroll
            for (int q = 0; q < NQ; q++) {
                acc[q] = f2add(acc[q], ((i >> (11 - q)) & 1) ? pn : p2);
            }
        }
#pragma unroll
        for (int q = 0; q < NQ; q++) {
#pragma unroll
            for (int o = 16; o; o >>= 1)
                acc[q] = f2add(acc[q], __shfl_xor_sync(0xffffffffu, acc[q], o));
        }
        if ((tid & 31) == 0) {
#pragma unroll
            for (int q = 0; q < NQ; q++) {
                float p0, p1; unpk2(acc[q], p0, p1);
                atomicAdd(&sAcc[2 * pk * NQ + q], p0);
                atomicAdd(&sAcc[(2 * pk + 1) * NQ + q], p1);
            }
        }
    }
    __syncthreads();
    if (tid < 4 * NQ) {
        out[(size_t)(4 * bid) * NQ + tid] = sAcc[tid];
    }
}

extern "C" void kernel_launch(void* const* d_in, const int* in_sizes, int n_in,
                              void* d_out, int out_size) {
    const float* x = (const float*)d_in[0];       // (8192, 4096) float32
    const float* params = (const float*)d_in[1];  // (108,) float32
    float* out = (float*)d_out;                   // (8192, 12) float32
    const int batch = in_sizes[0] / DIM;
    const int smem_bytes = 4 * BUF * (int)sizeof(u64); // 147456

    cudaFuncSetAttribute(qsim_kernel, cudaFuncAttributeMaxDynamicSharedMemorySize,
                         smem_bytes);
    prep_gates<<<1, 64>>>(params);
    qsim_kernel<<<batch / 4, TPB, smem_bytes>>>(x, out);
}

// round 12
// speedup vs baseline: 1.0319x; 1.0319x over previous
#include <cuda_runtime.h>

#define NQ 12
#define DIM 4096
#define NLAYERS 3
#define NGATES (NLAYERS * NQ)   // 36
#define TPB 512
#define RPT 8                   // register amplitudes per thread (per packed pair)
#define STRIDE 9                // padded smem row stride (in 8-byte units)
#define BUF (TPB * STRIDE)      // 4608 u64 per component per buffer

typedef unsigned long long u64;

// Pre-packed gate coefficients: 36 gates x 12 float2 (duplicated / negated-duplicated)
__device__ float2 g_gates2[NGATES * 12];

// ---------------- f32x2 helpers (sm_103a packed fp32) ----------------
__device__ __forceinline__ u64 pk2(float x, float y) {
    u64 r; asm("mov.b64 %0, {%1, %2};" : "=l"(r) : "f"(x), "f"(y)); return r;
}
__device__ __forceinline__ void unpk2(u64 a, float& x, float& y) {
    asm("mov.b64 {%0, %1}, %2;" : "=f"(x), "=f"(y) : "l"(a));
}
__device__ __forceinline__ u64 f2fma(u64 a, u64 b, u64 c) {
    u64 d; asm("fma.rn.f32x2 %0, %1, %2, %3;" : "=l"(d) : "l"(a), "l"(b), "l"(c)); return d;
}
__device__ __forceinline__ u64 f2mul(u64 a, u64 b) {
    u64 d; asm("mul.rn.f32x2 %0, %1, %2;" : "=l"(d) : "l"(a), "l"(b)); return d;
}
__device__ __forceinline__ u64 f2add(u64 a, u64 b) {
    u64 d; asm("add.rn.f32x2 %0, %1, %2;" : "=l"(d) : "l"(a), "l"(b)); return d;
}
__device__ __forceinline__ void bar64(int id) {
    asm volatile("bar.sync %0, 64;" :: "r"(id) : "memory");
}

// ---------------------------------------------------------------------------
// Prep: fuse RZ*RY*RX per gate; emit 12 duplicated-packed coefficient pairs.
// ---------------------------------------------------------------------------
__global__ void prep_gates(const float* __restrict__ params) {
    int g = blockIdx.x * blockDim.x + threadIdx.x;
    if (g >= NGATES) return;
    float a = params[3 * g + 0] * 0.5f;
    float b = params[3 * g + 1] * 0.5f;
    float c = params[3 * g + 2] * 0.5f;
    float ca = cosf(a), sa = sinf(a);
    float cb = cosf(b), sb = sinf(b);
    float cc = cosf(c), sc = sinf(c);
    float m00r = cb * ca, m00i = sb * sa;
    float m01r = -sb * ca, m01i = -cb * sa;
    float m10r = sb * ca, m10i = -cb * sa;
    float m11r = cb * ca, m11i = -sb * sa;
    float u00r = cc * m00r + sc * m00i, u00i = cc * m00i - sc * m00r;
    float u01r = cc * m01r + sc * m01i, u01i = cc * m01i - sc * m01r;
    float u10r = cc * m10r - sc * m10i, u10i = cc * m10i + sc * m10r;
    float u11r = cc * m11r - sc * m11i, u11i = cc * m11i + sc * m11r;
    float2* o = &g_gates2[g * 12];
    o[0]  = make_float2(u00r, u00r);
    o[1]  = make_float2(-u00i, -u00i);
    o[2]  = make_float2(u01r, u01r);
    o[3]  = make_float2(-u01i, -u01i);
    o[4]  = make_float2(u00i, u00i);
    o[5]  = make_float2(u01i, u01i);
    o[6]  = make_float2(u10r, u10r);
    o[7]  = make_float2(-u10i, -u10i);
    o[8]  = make_float2(u11r, u11r);
    o[9]  = make_float2(-u11i, -u11i);
    o[10] = make_float2(u10i, u10i);
    o[11] = make_float2(u11i, u11i);
}

// Apply the 3 gates on register-index bits, in mb order 1,2,4 (commuting gates;
// low-mb first so computation starts as soon as the first loads land).
// Gate on mb = 1<<s is gate index (gbase + 2 - s).
__device__ __forceinline__ void apply3r(u64 vre[RPT], u64 vim[RPT],
                                        const u64* __restrict__ sG2, int gbase) {
#pragma unroll
    for (int s = 0; s < 3; s++) {
        const u64* C = &sG2[(gbase + 2 - s) * 12];
        const u64 c0 = C[0], c1 = C[1], c2 = C[2], c3 = C[3], c4 = C[4], c5 = C[5];
        const u64 c6 = C[6], c7 = C[7], c8 = C[8], c9 = C[9], c10 = C[10], c11 = C[11];
        const int mb = 1 << s;
#pragma unroll
        for (int r = 0; r < RPT; r++) {
            if (!(r & mb)) {
                const int r1 = r | mb;
                u64 a0re = vre[r],  a0im = vim[r];
                u64 a1re = vre[r1], a1im = vim[r1];
                vre[r]  = f2fma(c0, a0re, f2fma(c1, a0im, f2fma(c2, a1re, f2mul(c3, a1im))));
                vim[r]  = f2fma(c4, a0re, f2fma(c0, a0im, f2fma(c5, a1re, f2mul(c2, a1im))));
                vre[r1] = f2fma(c6, a0re, f2fma(c7, a0im, f2fma(c8, a1re, f2mul(c9, a1im))));
                vim[r1] = f2fma(c10, a0re, f2fma(c6, a0im, f2fma(c11, a1re, f2mul(c8, a1im))));
            }
        }
    }
}

// ---------------------------------------------------------------------------
// One CTA per BATCH PAIR (u64 packs elt0,elt1). 512 thr x 8 packed amps.
// Layouts: L0 r={b11,b10,b9} | L1 r={b8,b7,b6} | L2 r={b5,b4,b3} | L3 r={b2,b1,b0}
// Sync scopes: X1 global (2x full) | X2 64-thread groups (2x bar64) |
// X3 in-warp (__syncwarp) | X4 own-rows + full barrier before sigma-gather.
// Last layer: X4/sigma SKIPPED — sigma folded into expectation signs via
// sigma^{-1} (XOR-linear).
// ---------------------------------------------------------------------------
extern __shared__ __align__(16) u64 dynsm[];

__global__ __launch_bounds__(TPB, 1) void qsim_kernel(
    const float* __restrict__ x, float* __restrict__ out) {
    __shared__ u64 sG2[NGATES * 12];
    __shared__ u64 sRed[TPB / 32];
    __shared__ float sAcc[2 * NQ];

    u64* bReA = dynsm;
    u64* bImA = dynsm + BUF;
    u64* bReB = dynsm + 2 * BUF;
    u64* bImB = dynsm + 3 * BUF;

    const int tid = threadIdx.x;
    const int bid = blockIdx.x;
    const float* xb0 = x + (size_t)(2 * bid) * DIM;
    const float* xb1 = xb0 + DIM;

    if (tid < NGATES * 12) sG2[tid] = ((const u64*)g_gates2)[tid];
    if (tid < 2 * NQ) sAcc[tid] = 0.0f;

    // ---- load both elements packed (L0) + per-element sum of squares ----
    u64 vre[RPT], vim[RPT];
    u64 ss = 0;
#pragma unroll
    for (int r = 0; r < RPT; r++) {
        int i = (r << 9) | tid;
        u64 v = pk2(xb0[i], xb1[i]);
        vre[r] = v;
        vim[r] = 0;
        ss = f2fma(v, v, ss);
    }
#pragma unroll
    for (int o = 16; o; o >>= 1) ss = f2add(ss, __shfl_xor_sync(0xffffffffu, ss, o));
    if ((tid & 31) == 0) sRed[tid >> 5] = ss;
    __syncthreads();
    ss = 0;
#pragma unroll
    for (int w = 0; w < TPB / 32; w++) ss = f2add(ss, sRed[w]);
    float s0, s1; unpk2(ss, s0, s1);
    const u64 inv = pk2(rsqrtf(s0), rsqrtf(s1));
#pragma unroll
    for (int r = 0; r < RPT; r++) vre[r] = f2mul(vre[r], inv);

    // exchange write bases (u64 units)
    const int base1 = (tid & 63) * STRIDE + ((tid >> 6) & 7);                      // +r*576
    const int base2 = (((tid >> 6) << 6) | (tid & 7)) * STRIDE + ((tid >> 3) & 7); // +r*72
    const int base3 = (tid >> 3) * (8 * STRIDE) + (tid & 7);                       // +r*9
    const int baseR = tid * STRIDE;                                                // canonical rows
    const int mybar = 1 + (tid >> 6);                                              // named barrier ids 1..8
    // sigma(t): XOR-linear CNOT-ring permutation (verified)
    const int sig_t = ((tid ^ (tid >> 1)) & 0x0FF) | (tid & 0x100)
                    | ((tid & 1) ? 0xC00 : 0);
    // sigma^{-1}(tid<<3): reverse CNOT ring applied in forward order
    int invt = tid << 3;
#pragma unroll
    for (int g = 0; g < NQ; g++) {
        const int bc = 11 - g;
        const int bt = 11 - ((g + 1) % NQ);
        invt ^= ((invt >> bc) & 1) << bt;
    }

    // ---- circuit ----
#pragma unroll 1
    for (int layer = 0; layer < NLAYERS; layer++) {
        const int gbase = layer * NQ;

        apply3r(vre, vim, sG2, gbase + 0);         // bits 11,10,9 (mb order 1,2,4)
        __syncthreads();                           // prior sigma-readers done
#pragma unroll
        for (int r = 0; r < RPT; r++) {            // X1 stores (global scatter) -> A
            int a = base1 + r * (64 * STRIDE);
            bReA[a] = vre[r]; bImA[a] = vim[r];
        }
        __syncthreads();
#pragma unroll
        for (int r = 0; r < RPT; r++) {            // X1 canonical reads
            int a = baseR + r;
            vre[r] = bReA[a]; vim[r] = bImA[a];
        }
        bar64(mybar);                              // 64-group reads done before X2/X3 stores

        apply3r(vre, vim, sG2, gbase + 3);         // bits 8,7,6
#pragma unroll
        for (int r = 0; r < RPT; r++) {            // X2 stores (64-group rows) -> B
            int a = base2 + r * (8 * STRIDE);
            bReB[a] = vre[r]; bImB[a] = vim[r];
        }
        bar64(mybar);
#pragma unroll
        for (int r = 0; r < RPT; r++) {
            int a = baseR + r;
            vre[r] = bReB[a]; vim[r] = bImB[a];
        }

        apply3r(vre, vim, sG2, gbase + 6);         // bits 5,4,3
#pragma unroll
        for (int r = 0; r < RPT; r++) {            // X3 stores (8-group, in-warp) -> A
            int a = base3 + r * STRIDE;
            bReA[a] = vre[r]; bImA[a] = vim[r];
        }
        __syncwarp();
#pragma unroll
        for (int r = 0; r < RPT; r++) {
            int a = baseR + r;
            vre[r] = bReA[a]; vim[r] = bImA[a];
        }

        apply3r(vre, vim, sG2, gbase + 9);         // bits 2,1,0
        if (layer < NLAYERS - 1) {
#pragma unroll
            for (int r = 0; r < RPT; r++) {        // X4 stores own rows -> B
                int a = baseR + r;
                bReB[a] = vre[r]; bImB[a] = vim[r];
            }
            __syncthreads();
            {
                // gather to L0 with CNOT-ring sigma folded in (verified constants)
                const int SIGC[RPT] = {0x000, 0x300, 0x600, 0x500,
                                       0xC00, 0xF00, 0xA00, 0x900};
#pragma unroll
                for (int r = 0; r < RPT; r++) {
                    int j = SIGC[r] ^ sig_t;
                    int a = j + (j >> 3);          // == (j>>3)*9 + (j&7)
                    vre[r] = bReB[a]; vim[r] = bImB[a];
                }
            }
        }
    }

    // ---- expectations, final sigma folded into signs via sigma^{-1} ----
    // Pre-sigma amp at L3 position j=(tid<<3)|r is the final amp at i=invsigma(j).
    // invsigma(j) = invt ^ INVC[r]  (XOR-linear; INVC = invsigma of r=0..7)
    u64 acc[NQ];
#pragma unroll
    for (int q = 0; q < NQ; q++) acc[q] = 0;
    {
        const int INVC[RPT] = {0x000, 0x801, 0x803, 0x002,
                               0x807, 0x006, 0x004, 0x805};
#pragma unroll
        for (int r = 0; r < RPT; r++) {
            u64 p2 = f2fma(vre[r], vre[r], f2mul(vim[r], vim[r]));
            u64 pn = p2 ^ 0x8000000080000000ULL;   // exact negation of both halves
            const int i = invt ^ INVC[r];
#pragma unroll
            for (int q = 0; q < NQ; q++) {
                acc[q] = f2add(acc[q], ((i >> (11 - q)) & 1) ? pn : p2);
            }
        }
    }
#pragma unroll
    for (int q = 0; q < NQ; q++) {
#pragma unroll
        for (int o = 16; o; o >>= 1)
            acc[q] = f2add(acc[q], __shfl_xor_sync(0xffffffffu, acc[q], o));
    }
    if ((tid & 31) == 0) {
#pragma unroll
        for (int q = 0; q < NQ; q++) {
            float p0, p1; unpk2(acc[q], p0, p1);
            atomicAdd(&sAcc[q], p0);
            atomicAdd(&sAcc[NQ + q], p1);
        }
    }
    __syncthreads();
    if (tid < NQ) {
        out[(size_t)(2 * bid) * NQ + tid] = sAcc[tid];
        out[(size_t)(2 * bid + 1) * NQ + tid] = sAcc[NQ + tid];
    }
}

extern "C" void kernel_launch(void* const* d_in, const int* in_sizes, int n_in,
                              void* d_out, int out_size) {
    const float* x = (const float*)d_in[0];       // (8192, 4096) float32
    const float* params = (const float*)d_in[1];  // (108,) float32
    float* out = (float*)d_out;                   // (8192, 12) float32
    const int batch = in_sizes[0] / DIM;
    const int smem_bytes = 4 * BUF * (int)sizeof(u64); // 147456

    cudaFuncSetAttribute(qsim_kernel, cudaFuncAttributeMaxDynamicSharedMemorySize,
                         smem_bytes);
    prep_gates<<<1, 64>>>(params);
    qsim_kernel<<<batch / 2, TPB, smem_bytes>>>(x, out);
}

// round 13
// speedup vs baseline: 1.0902x; 1.0565x over previous
#include <cuda_runtime.h>

#define NQ 12
#define DIM 4096
#define NLAYERS 3
#define NGATES (NLAYERS * NQ)   // 36
#define TPB 512
#define RPT 8                   // register amplitudes per thread (per packed pair)
#define STRIDE 9                // padded smem row stride (in 8-byte units)
#define BUF (TPB * STRIDE)      // 4608 u64 per component per buffer

typedef unsigned long long u64;

// Pre-packed gate coefficients: 36 gates x 12 float2 (duplicated / negated-duplicated)
__device__ float2 g_gates2[NGATES * 12];

// ---------------- f32x2 helpers (sm_103a packed fp32) ----------------
__device__ __forceinline__ u64 pk2(float x, float y) {
    u64 r; asm("mov.b64 %0, {%1, %2};" : "=l"(r) : "f"(x), "f"(y)); return r;
}
__device__ __forceinline__ void unpk2(u64 a, float& x, float& y) {
    asm("mov.b64 {%0, %1}, %2;" : "=f"(x), "=f"(y) : "l"(a));
}
__device__ __forceinline__ u64 f2fma(u64 a, u64 b, u64 c) {
    u64 d; asm("fma.rn.f32x2 %0, %1, %2, %3;" : "=l"(d) : "l"(a), "l"(b), "l"(c)); return d;
}
__device__ __forceinline__ u64 f2mul(u64 a, u64 b) {
    u64 d; asm("mul.rn.f32x2 %0, %1, %2;" : "=l"(d) : "l"(a), "l"(b)); return d;
}
__device__ __forceinline__ u64 f2add(u64 a, u64 b) {
    u64 d; asm("add.rn.f32x2 %0, %1, %2;" : "=l"(d) : "l"(a), "l"(b)); return d;
}
__device__ __forceinline__ void bar64(int id) {
    asm volatile("bar.sync %0, 64;" :: "r"(id) : "memory");
}

// ---------------------------------------------------------------------------
// Prep: fuse RZ*RY*RX per gate; emit 12 duplicated-packed coefficient pairs.
// ---------------------------------------------------------------------------
__global__ void prep_gates(const float* __restrict__ params) {
    int g = blockIdx.x * blockDim.x + threadIdx.x;
    if (g >= NGATES) return;
    float a = params[3 * g + 0] * 0.5f;
    float b = params[3 * g + 1] * 0.5f;
    float c = params[3 * g + 2] * 0.5f;
    float ca = cosf(a), sa = sinf(a);
    float cb = cosf(b), sb = sinf(b);
    float cc = cosf(c), sc = sinf(c);
    float m00r = cb * ca, m00i = sb * sa;
    float m01r = -sb * ca, m01i = -cb * sa;
    float m10r = sb * ca, m10i = -cb * sa;
    float m11r = cb * ca, m11i = -sb * sa;
    float u00r = cc * m00r + sc * m00i, u00i = cc * m00i - sc * m00r;
    float u01r = cc * m01r + sc * m01i, u01i = cc * m01i - sc * m01r;
    float u10r = cc * m10r - sc * m10i, u10i = cc * m10i + sc * m10r;
    float u11r = cc * m11r - sc * m11i, u11i = cc * m11i + sc * m11r;
    float2* o = &g_gates2[g * 12];
    o[0]  = make_float2(u00r, u00r);
    o[1]  = make_float2(-u00i, -u00i);
    o[2]  = make_float2(u01r, u01r);
    o[3]  = make_float2(-u01i, -u01i);
    o[4]  = make_float2(u00i, u00i);
    o[5]  = make_float2(u01i, u01i);
    o[6]  = make_float2(u10r, u10r);
    o[7]  = make_float2(-u10i, -u10i);
    o[8]  = make_float2(u11r, u11r);
    o[9]  = make_float2(-u11i, -u11i);
    o[10] = make_float2(u10i, u10i);
    o[11] = make_float2(u11i, u11i);
}

// Apply the 3 gates whose qubit bits are the register-index bits (bit2,1,0 of r).
// (R7-identical: mb order 4,2,1.)
__device__ __forceinline__ void apply3(u64 vre[RPT], u64 vim[RPT],
                                       const u64* __restrict__ sG2, int gbase) {
#pragma unroll
    for (int qq = 0; qq < 3; qq++) {
        const u64* C = &sG2[(gbase + qq) * 12];
        const u64 c0 = C[0], c1 = C[1], c2 = C[2], c3 = C[3], c4 = C[4], c5 = C[5];
        const u64 c6 = C[6], c7 = C[7], c8 = C[8], c9 = C[9], c10 = C[10], c11 = C[11];
        const int mb = 4 >> qq;
#pragma unroll
        for (int r = 0; r < RPT; r++) {
            if (!(r & mb)) {
                const int r1 = r | mb;
                u64 a0re = vre[r],  a0im = vim[r];
                u64 a1re = vre[r1], a1im = vim[r1];
                u64 n0re = f2fma(c0, a0re, f2fma(c1, a0im, f2fma(c2, a1re, f2mul(c3, a1im))));
                u64 n0im = f2fma(c4, a0re, f2fma(c0, a0im, f2fma(c5, a1re, f2mul(c2, a1im))));
                u64 n1re = f2fma(c6, a0re, f2fma(c7, a0im, f2fma(c8, a1re, f2mul(c9, a1im))));
                u64 n1im = f2fma(c10, a0re, f2fma(c6, a0im, f2fma(c11, a1re, f2mul(c8, a1im))));
                vre[r] = n0re; vim[r] = n0im;
                vre[r1] = n1re; vim[r1] = n1im;
            }
        }
    }
}

// ---------------------------------------------------------------------------
// One CTA per BATCH PAIR (u64 packs elt0,elt1). 512 thr x 8 packed amps.
// Layouts: L0 r={b11,b10,b9} | L1 r={b8,b7,b6} | L2 r={b5,b4,b3} | L3 r={b2,b1,b0}
// Exchange scopes (R7-identical):
//   X1 (L0->L1): global  -> __syncthreads      (buffer A)
//   X2 (L1->L2): 64-grp  -> bar.sync 64        (buffer B)
//   X3 (L2->L3): 8-grp   -> __syncwarp         (buffer A)
//   X4 (L3->L0 + sigma): global -> __syncthreads (buffer B)
// NEW vs R7: last layer skips X4 entirely — sigma folded into expectation
// signs via sigma^{-1} (XOR-linear; constants HW-validated in R9's run).
// ---------------------------------------------------------------------------
extern __shared__ __align__(16) u64 dynsm[];

__global__ __launch_bounds__(TPB, 1) void qsim_kernel(
    const float* __restrict__ x, float* __restrict__ out) {
    __shared__ u64 sG2[NGATES * 12];
    __shared__ u64 sRed[TPB / 32];
    __shared__ float sAcc[2 * NQ];

    u64* bReA = dynsm;
    u64* bImA = dynsm + BUF;
    u64* bReB = dynsm + 2 * BUF;
    u64* bImB = dynsm + 3 * BUF;

    const int tid = threadIdx.x;
    const int bid = blockIdx.x;
    const float* xb0 = x + (size_t)(2 * bid) * DIM;
    const float* xb1 = xb0 + DIM;

    if (tid < NGATES * 12) sG2[tid] = ((const u64*)g_gates2)[tid];
    if (tid < 2 * NQ) sAcc[tid] = 0.0f;

    // ---- load both elements packed (L0) + per-element sum of squares ----
    u64 vre[RPT], vim[RPT];
    u64 ss = 0;
#pragma unroll
    for (int r = 0; r < RPT; r++) {
        int i = (r << 9) | tid;
        u64 v = pk2(xb0[i], xb1[i]);
        vre[r] = v;
        vim[r] = 0;
        ss = f2fma(v, v, ss);
    }
#pragma unroll
    for (int o = 16; o; o >>= 1) ss = f2add(ss, __shfl_xor_sync(0xffffffffu, ss, o));
    if ((tid & 31) == 0) sRed[tid >> 5] = ss;
    __syncthreads();
    ss = 0;
#pragma unroll
    for (int w = 0; w < TPB / 32; w++) ss = f2add(ss, sRed[w]);
    float s0, s1; unpk2(ss, s0, s1);
    const u64 inv = pk2(rsqrtf(s0), rsqrtf(s1));
#pragma unroll
    for (int r = 0; r < RPT; r++) vre[r] = f2mul(vre[r], inv);

    // exchange write bases (u64 units)
    const int base1 = (tid & 63) * STRIDE + ((tid >> 6) & 7);                      // +r*576
    const int base2 = (((tid >> 6) << 6) | (tid & 7)) * STRIDE + ((tid >> 3) & 7); // +r*72
    const int base3 = (tid >> 3) * (8 * STRIDE) + (tid & 7);                       // +r*9
    const int baseR = tid * STRIDE;                                                // canonical rows
    const int mybar = 1 + (tid >> 6);                                              // named barrier id 1..8
    // sigma(t): XOR-linear CNOT-ring permutation (verified)
    const int sig_t = ((tid ^ (tid >> 1)) & 0x0FF) | (tid & 0x100)
                    | ((tid & 1) ? 0xC00 : 0);
    // sigma^{-1}(tid<<3): reverse CNOT ring applied in forward order
    int invt = tid << 3;
#pragma unroll
    for (int g = 0; g < NQ; g++) {
        const int bc = 11 - g;
        const int bt = 11 - ((g + 1) % NQ);
        invt ^= ((invt >> bc) & 1) << bt;
    }

    // ---- circuit ----
#pragma unroll 1
    for (int layer = 0; layer < NLAYERS; layer++) {
        const int gbase = layer * NQ;

        apply3(vre, vim, sG2, gbase + 0);          // bits 11,10,9
#pragma unroll
        for (int r = 0; r < RPT; r++) {            // X1 write -> A (global shuffle)
            int a = base1 + r * (64 * STRIDE);
            bReA[a] = vre[r]; bImA[a] = vim[r];
        }
        __syncthreads();
#pragma unroll
        for (int r = 0; r < RPT; r++) {
            int a = baseR + r;
            vre[r] = bReA[a]; vim[r] = bImA[a];
        }

        apply3(vre, vim, sG2, gbase + 3);          // bits 8,7,6
#pragma unroll
        for (int r = 0; r < RPT; r++) {            // X2 write -> B (64-thread groups)
            int a = base2 + r * (8 * STRIDE);
            bReB[a] = vre[r]; bImB[a] = vim[r];
        }
        bar64(mybar);
#pragma unroll
        for (int r = 0; r < RPT; r++) {
            int a = baseR + r;
            vre[r] = bReB[a]; vim[r] = bImB[a];
        }

        apply3(vre, vim, sG2, gbase + 6);          // bits 5,4,3
#pragma unroll
        for (int r = 0; r < RPT; r++) {            // X3 write -> A (8-thread groups, in-warp)
            int a = base3 + r * STRIDE;
            bReA[a] = vre[r]; bImA[a] = vim[r];
        }
        __syncwarp();
#pragma unroll
        for (int r = 0; r < RPT; r++) {
            int a = baseR + r;
            vre[r] = bReA[a]; vim[r] = bImA[a];
        }

        apply3(vre, vim, sG2, gbase + 9);          // bits 2,1,0
        if (layer < NLAYERS - 1) {
#pragma unroll
            for (int r = 0; r < RPT; r++) {        // X4 write -> B (own rows only)
                int a = baseR + r;
                bReB[a] = vre[r]; bImB[a] = vim[r];
            }
            __syncthreads();
            {
                // gather to L0 with CNOT-ring sigma folded in (verified constants)
                const int SIGC[RPT] = {0x000, 0x300, 0x600, 0x500,
                                       0xC00, 0xF00, 0xA00, 0x900};
#pragma unroll
                for (int r = 0; r < RPT; r++) {
                    int j = SIGC[r] ^ sig_t;
                    int a = j + (j >> 3);          // == (j>>3)*9 + (j&7)
                    vre[r] = bReB[a]; vim[r] = bImB[a];
                }
            }
        }
    }

    // ---- expectations, final sigma folded into signs via sigma^{-1} ----
    // Pre-sigma amp at L3 position j=(tid<<3)|r is the final amp at i=invsigma(j).
    // invsigma(j) = invt ^ INVC[r]  (XOR-linear; HW-validated in R9 run)
    u64 acc[NQ];
#pragma unroll
    for (int q = 0; q < NQ; q++) acc[q] = 0;
    {
        const int INVC[RPT] = {0x000, 0x801, 0x803, 0x002,
                               0x807, 0x006, 0x004, 0x805};
#pragma unroll
        for (int r = 0; r < RPT; r++) {
            u64 p2 = f2fma(vre[r], vre[r], f2mul(vim[r], vim[r]));
            u64 pn = p2 ^ 0x8000000080000000ULL;   // exact negation of both halves
            const int i = invt ^ INVC[r];
#pragma unroll
            for (int q = 0; q < NQ; q++) {
                acc[q] = f2add(acc[q], ((i >> (11 - q)) & 1) ? pn : p2);
            }
        }
    }
#pragma unroll
    for (int q = 0; q < NQ; q++) {
#pragma unroll
        for (int o = 16; o; o >>= 1)
            acc[q] = f2add(acc[q], __shfl_xor_sync(0xffffffffu, acc[q], o));
    }
    if ((tid & 31) == 0) {
#pragma unroll
        for (int q = 0; q < NQ; q++) {
            float p0, p1; unpk2(acc[q], p0, p1);
            atomicAdd(&sAcc[q], p0);
            atomicAdd(&sAcc[NQ + q], p1);
        }
    }
    __syncthreads();
    if (tid < NQ) {
        out[(size_t)(2 * bid) * NQ + tid] = sAcc[tid];
        out[(size_t)(2 * bid + 1) * NQ + tid] = sAcc[NQ + tid];
    }
}

extern "C" void kernel_launch(void* const* d_in, const int* in_sizes, int n_in,
                              void* d_out, int out_size) {
    const float* x = (const float*)d_in[0];       // (8192, 4096) float32
    const float* params = (const float*)d_in[1];  // (108,) float32
    float* out = (float*)d_out;                   // (8192, 12) float32
    const int batch = in_sizes[0] / DIM;
    const int smem_bytes = 4 * BUF * (int)sizeof(u64); // 147456

    cudaFuncSetAttribute(qsim_kernel, cudaFuncAttributeMaxDynamicSharedMemorySize,
                         smem_bytes);
    prep_gates<<<1, 64>>>(params);
    qsim_kernel<<<batch / 2, TPB, smem_bytes>>>(x, out);
}

// round 14
// speedup vs baseline: 1.1583x; 1.0624x over previous
#include <cuda_runtime.h>

#define NQ 12
#define DIM 4096
#define NLAYERS 3
#define NGATES (NLAYERS * NQ)   // 36
#define TPB 512
#define RPT 8                   // register amplitudes per thread (per packed pair)
#define STRIDE 9                // padded smem row stride (in 16-byte units)
#define BUF (TPB * STRIDE)      // 4608 ulonglong2 (re,im pairs) per buffer

typedef unsigned long long u64;

// Pre-packed gate coefficients: 36 gates x 12 float2 (duplicated / negated-duplicated)
__device__ float2 g_gates2[NGATES * 12];

// ---------------- f32x2 helpers (sm_103a packed fp32) ----------------
__device__ __forceinline__ u64 pk2(float x, float y) {
    u64 r; asm("mov.b64 %0, {%1, %2};" : "=l"(r) : "f"(x), "f"(y)); return r;
}
__device__ __forceinline__ void unpk2(u64 a, float& x, float& y) {
    asm("mov.b64 {%0, %1}, %2;" : "=f"(x), "=f"(y) : "l"(a));
}
__device__ __forceinline__ u64 f2fma(u64 a, u64 b, u64 c) {
    u64 d; asm("fma.rn.f32x2 %0, %1, %2, %3;" : "=l"(d) : "l"(a), "l"(b), "l"(c)); return d;
}
__device__ __forceinline__ u64 f2mul(u64 a, u64 b) {
    u64 d; asm("mul.rn.f32x2 %0, %1, %2;" : "=l"(d) : "l"(a), "l"(b)); return d;
}
__device__ __forceinline__ u64 f2add(u64 a, u64 b) {
    u64 d; asm("add.rn.f32x2 %0, %1, %2;" : "=l"(d) : "l"(a), "l"(b)); return d;
}
__device__ __forceinline__ void bar64(int id) {
    asm volatile("bar.sync %0, 64;" :: "r"(id) : "memory");
}

// ---------------------------------------------------------------------------
// Prep: fuse RZ*RY*RX per gate; emit 12 duplicated-packed coefficient pairs.
// ---------------------------------------------------------------------------
__global__ void prep_gates(const float* __restrict__ params) {
    int g = blockIdx.x * blockDim.x + threadIdx.x;
    if (g >= NGATES) return;
    float a = params[3 * g + 0] * 0.5f;
    float b = params[3 * g + 1] * 0.5f;
    float c = params[3 * g + 2] * 0.5f;
    float ca = cosf(a), sa = sinf(a);
    float cb = cosf(b), sb = sinf(b);
    float cc = cosf(c), sc = sinf(c);
    float m00r = cb * ca, m00i = sb * sa;
    float m01r = -sb * ca, m01i = -cb * sa;
    float m10r = sb * ca, m10i = -cb * sa;
    float m11r = cb * ca, m11i = -sb * sa;
    float u00r = cc * m00r + sc * m00i, u00i = cc * m00i - sc * m00r;
    float u01r = cc * m01r + sc * m01i, u01i = cc * m01i - sc * m01r;
    float u10r = cc * m10r - sc * m10i, u10i = cc * m10i + sc * m10r;
    float u11r = cc * m11r - sc * m11i, u11i = cc * m11i + sc * m11r;
    float2* o = &g_gates2[g * 12];
    o[0]  = make_float2(u00r, u00r);
    o[1]  = make_float2(-u00i, -u00i);
    o[2]  = make_float2(u01r, u01r);
    o[3]  = make_float2(-u01i, -u01i);
    o[4]  = make_float2(u00i, u00i);
    o[5]  = make_float2(u01i, u01i);
    o[6]  = make_float2(u10r, u10r);
    o[7]  = make_float2(-u10i, -u10i);
    o[8]  = make_float2(u11r, u11r);
    o[9]  = make_float2(-u11i, -u11i);
    o[10] = make_float2(u10i, u10i);
    o[11] = make_float2(u11i, u11i);
}

// Apply the 3 gates whose qubit bits are the register-index bits (bit2,1,0 of r).
__device__ __forceinline__ void apply3(u64 vre[RPT], u64 vim[RPT],
                                       const u64* __restrict__ sG2, int gbase) {
#pragma unroll
    for (int qq = 0; qq < 3; qq++) {
        const u64* C = &sG2[(gbase + qq) * 12];
        const u64 c0 = C[0], c1 = C[1], c2 = C[2], c3 = C[3], c4 = C[4], c5 = C[5];
        const u64 c6 = C[6], c7 = C[7], c8 = C[8], c9 = C[9], c10 = C[10], c11 = C[11];
        const int mb = 4 >> qq;
#pragma unroll
        for (int r = 0; r < RPT; r++) {
            if (!(r & mb)) {
                const int r1 = r | mb;
                u64 a0re = vre[r],  a0im = vim[r];
                u64 a1re = vre[r1], a1im = vim[r1];
                u64 n0re = f2fma(c0, a0re, f2fma(c1, a0im, f2fma(c2, a1re, f2mul(c3, a1im))));
                u64 n0im = f2fma(c4, a0re, f2fma(c0, a0im, f2fma(c5, a1re, f2mul(c2, a1im))));
                u64 n1re = f2fma(c6, a0re, f2fma(c7, a0im, f2fma(c8, a1re, f2mul(c9, a1im))));
                u64 n1im = f2fma(c10, a0re, f2fma(c6, a0im, f2fma(c11, a1re, f2mul(c8, a1im))));
                vre[r] = n0re; vim[r] = n0im;
                vre[r1] = n1re; vim[r1] = n1im;
            }
        }
    }
}

// ---------------------------------------------------------------------------
// One CTA per BATCH PAIR (u64 packs elt0,elt1). 512 thr x 8 packed amps.
// NEW vs 551us kernel: (re,im) interleaved as one ulonglong2 per amplitude —
// every exchange transfer is a single STS.128/LDS.128 (half the smem insts,
// same bytes). All index math unchanged (now in 16-byte units); verified
// conflict-free per 8-lane phase for every exchange pattern incl. sigma.
// Layouts: L0 r={b11,b10,b9} | L1 r={b8,b7,b6} | L2 r={b5,b4,b3} | L3 r={b2,b1,b0}
// Sync scopes: X1 global (syncthreads) | X2 64-grp (bar64) | X3 in-warp
// (syncwarp) | X4 own-rows + syncthreads + sigma-gather (layers 0,1 only;
// last layer folds sigma into expectation signs via sigma^{-1}).
// ---------------------------------------------------------------------------
extern __shared__ __align__(16) ulonglong2 dynsm2[];

__global__ __launch_bounds__(TPB, 1) void qsim_kernel(
    const float* __restrict__ x, float* __restrict__ out) {
    __shared__ u64 sG2[NGATES * 12];
    __shared__ u64 sRed[TPB / 32];
    __shared__ float sAcc[2 * NQ];

    ulonglong2* bA = dynsm2;
    ulonglong2* bB = dynsm2 + BUF;

    const int tid = threadIdx.x;
    const int bid = blockIdx.x;
    const float* xb0 = x + (size_t)(2 * bid) * DIM;
    const float* xb1 = xb0 + DIM;

    if (tid < NGATES * 12) sG2[tid] = ((const u64*)g_gates2)[tid];
    if (tid < 2 * NQ) sAcc[tid] = 0.0f;

    // ---- load both elements packed (L0) + per-element sum of squares ----
    u64 vre[RPT], vim[RPT];
    u64 ss = 0;
#pragma unroll
    for (int r = 0; r < RPT; r++) {
        int i = (r << 9) | tid;
        u64 v = pk2(xb0[i], xb1[i]);
        vre[r] = v;
        vim[r] = 0;
        ss = f2fma(v, v, ss);
    }
#pragma unroll
    for (int o = 16; o; o >>= 1) ss = f2add(ss, __shfl_xor_sync(0xffffffffu, ss, o));
    if ((tid & 31) == 0) sRed[tid >> 5] = ss;
    __syncthreads();
    ss = 0;
#pragma unroll
    for (int w = 0; w < TPB / 32; w++) ss = f2add(ss, sRed[w]);
    float s0, s1; unpk2(ss, s0, s1);
    const u64 inv = pk2(rsqrtf(s0), rsqrtf(s1));
#pragma unroll
    for (int r = 0; r < RPT; r++) vre[r] = f2mul(vre[r], inv);

    // exchange write bases (16-byte element units)
    const int base1 = (tid & 63) * STRIDE + ((tid >> 6) & 7);                      // +r*576
    const int base2 = (((tid >> 6) << 6) | (tid & 7)) * STRIDE + ((tid >> 3) & 7); // +r*72
    const int base3 = (tid >> 3) * (8 * STRIDE) + (tid & 7);                       // +r*9
    const int baseR = tid * STRIDE;                                                // canonical rows
    const int mybar = 1 + (tid >> 6);                                              // named barrier id 1..8
    // sigma(t): XOR-linear CNOT-ring permutation (verified)
    const int sig_t = ((tid ^ (tid >> 1)) & 0x0FF) | (tid & 0x100)
                    | ((tid & 1) ? 0xC00 : 0);
    // sigma^{-1}(tid<<3): reverse CNOT ring applied in forward order
    int invt = tid << 3;
#pragma unroll
    for (int g = 0; g < NQ; g++) {
        const int bc = 11 - g;
        const int bt = 11 - ((g + 1) % NQ);
        invt ^= ((invt >> bc) & 1) << bt;
    }

    // ---- circuit ----
#pragma unroll 1
    for (int layer = 0; layer < NLAYERS; layer++) {
        const int gbase = layer * NQ;

        apply3(vre, vim, sG2, gbase + 0);          // bits 11,10,9
#pragma unroll
        for (int r = 0; r < RPT; r++) {            // X1 write -> A (global shuffle)
            int a = base1 + r * (64 * STRIDE);
            bA[a] = make_ulonglong2(vre[r], vim[r]);
        }
        __syncthreads();
#pragma unroll
        for (int r = 0; r < RPT; r++) {
            ulonglong2 v = bA[baseR + r];
            vre[r] = v.x; vim[r] = v.y;
        }

        apply3(vre, vim, sG2, gbase + 3);          // bits 8,7,6
#pragma unroll
        for (int r = 0; r < RPT; r++) {            // X2 write -> B (64-thread groups)
            int a = base2 + r * (8 * STRIDE);
            bB[a] = make_ulonglong2(vre[r], vim[r]);
        }
        bar64(mybar);
#pragma unroll
        for (int r = 0; r < RPT; r++) {
            ulonglong2 v = bB[baseR + r];
            vre[r] = v.x; vim[r] = v.y;
        }

        apply3(vre, vim, sG2, gbase + 6);          // bits 5,4,3
#pragma unroll
        for (int r = 0; r < RPT; r++) {            // X3 write -> A (8-thread groups, in-warp)
            int a = base3 + r * STRIDE;
            bA[a] = make_ulonglong2(vre[r], vim[r]);
        }
        __syncwarp();
#pragma unroll
        for (int r = 0; r < RPT; r++) {
            ulonglong2 v = bA[baseR + r];
            vre[r] = v.x; vim[r] = v.y;
        }

        apply3(vre, vim, sG2, gbase + 9);          // bits 2,1,0
        if (layer < NLAYERS - 1) {
#pragma unroll
            for (int r = 0; r < RPT; r++) {        // X4 write -> B (own rows only)
                bB[baseR + r] = make_ulonglong2(vre[r], vim[r]);
            }
            __syncthreads();
            {
                // gather to L0 with CNOT-ring sigma folded in (verified constants)
                const int SIGC[RPT] = {0x000, 0x300, 0x600, 0x500,
                                       0xC00, 0xF00, 0xA00, 0x900};
#pragma unroll
                for (int r = 0; r < RPT; r++) {
                    int j = SIGC[r] ^ sig_t;
                    int a = j + (j >> 3);          // == (j>>3)*9 + (j&7)
                    ulonglong2 v = bB[a];
                    vre[r] = v.x; vim[r] = v.y;
                }
            }
        }
    }

    // ---- expectations, final sigma folded into signs via sigma^{-1} ----
    // Pre-sigma amp at L3 position j=(tid<<3)|r is the final amp at i=invsigma(j).
    // invsigma(j) = invt ^ INVC[r]  (XOR-linear; HW-validated)
    u64 acc[NQ];
#pragma unroll
    for (int q = 0; q < NQ; q++) acc[q] = 0;
    {
        const int INVC[RPT] = {0x000, 0x801, 0x803, 0x002,
                               0x807, 0x006, 0x004, 0x805};
#pragma unroll
        for (int r = 0; r < RPT; r++) {
            u64 p2 = f2fma(vre[r], vre[r], f2mul(vim[r], vim[r]));
            u64 pn = p2 ^ 0x8000000080000000ULL;   // exact negation of both halves
            const int i = invt ^ INVC[r];
#pragma unroll
            for (int q = 0; q < NQ; q++) {
                acc[q] = f2add(acc[q], ((i >> (11 - q)) & 1) ? pn : p2);
            }
        }
    }
#pragma unroll
    for (int q = 0; q < NQ; q++) {
#pragma unroll
        for (int o = 16; o; o >>= 1)
            acc[q] = f2add(acc[q], __shfl_xor_sync(0xffffffffu, acc[q], o));
    }
    if ((tid & 31) == 0) {
#pragma unroll
        for (int q = 0; q < NQ; q++) {
            float p0, p1; unpk2(acc[q], p0, p1);
            atomicAdd(&sAcc[q], p0);
            atomicAdd(&sAcc[NQ + q], p1);
        }
    }
    __syncthreads();
    if (tid < NQ) {
        out[(size_t)(2 * bid) * NQ + tid] = sAcc[tid];
        out[(size_t)(2 * bid + 1) * NQ + tid] = sAcc[NQ + tid];
    }
}

extern "C" void kernel_launch(void* const* d_in, const int* in_sizes, int n_in,
                              void* d_out, int out_size) {
    const float* x = (const float*)d_in[0];       // (8192, 4096) float32
    const float* params = (const float*)d_in[1];  // (108,) float32
    float* out = (float*)d_out;                   // (8192, 12) float32
    const int batch = in_sizes[0] / DIM;
    const int smem_bytes = 2 * BUF * (int)sizeof(ulonglong2); // 147456

    cudaFuncSetAttribute(qsim_kernel, cudaFuncAttributeMaxDynamicSharedMemorySize,
                         smem_bytes);
    prep_gates<<<1, 64>>>(params);
    qsim_kernel<<<batch / 2, TPB, smem_bytes>>>(x, out);
}

// round 15
// speedup vs baseline: 1.2019x; 1.0377x over previous
#include <cuda_runtime.h>

#define NQ 12
#define DIM 4096
#define NLAYERS 3
#define NGATES (NLAYERS * NQ)   // 36
#define TPB 512
#define RPT 8                   // register amplitudes per thread (per packed pair)
#define STRIDE 9                // padded smem row stride (in 16-byte units)
#define BUF (TPB * STRIDE)      // 4608 ulonglong2 (re,im pairs) per buffer

typedef unsigned long long u64;

// Pre-packed gate coefficients: 36 gates x 12 float2 (duplicated / negated-duplicated)
__device__ float2 g_gates2[NGATES * 12];

// ---------------- f32x2 helpers (sm_103a packed fp32) ----------------
__device__ __forceinline__ u64 pk2(float x, float y) {
    u64 r; asm("mov.b64 %0, {%1, %2};" : "=l"(r) : "f"(x), "f"(y)); return r;
}
__device__ __forceinline__ void unpk2(u64 a, float& x, float& y) {
    asm("mov.b64 {%0, %1}, %2;" : "=f"(x), "=f"(y) : "l"(a));
}
__device__ __forceinline__ u64 f2fma(u64 a, u64 b, u64 c) {
    u64 d; asm("fma.rn.f32x2 %0, %1, %2, %3;" : "=l"(d) : "l"(a), "l"(b), "l"(c)); return d;
}
__device__ __forceinline__ u64 f2mul(u64 a, u64 b) {
    u64 d; asm("mul.rn.f32x2 %0, %1, %2;" : "=l"(d) : "l"(a), "l"(b)); return d;
}
__device__ __forceinline__ u64 f2add(u64 a, u64 b) {
    u64 d; asm("add.rn.f32x2 %0, %1, %2;" : "=l"(d) : "l"(a), "l"(b)); return d;
}
__device__ __forceinline__ void bar64(int id) {
    asm volatile("bar.sync %0, 64;" :: "r"(id) : "memory");
}

// ---------------------------------------------------------------------------
// Prep: fuse RZ*RY*RX per gate; emit 12 duplicated-packed coefficient pairs.
// ---------------------------------------------------------------------------
__global__ void prep_gates(const float* __restrict__ params) {
    int g = blockIdx.x * blockDim.x + threadIdx.x;
    if (g >= NGATES) return;
    float a = params[3 * g + 0] * 0.5f;
    float b = params[3 * g + 1] * 0.5f;
    float c = params[3 * g + 2] * 0.5f;
    float ca = cosf(a), sa = sinf(a);
    float cb = cosf(b), sb = sinf(b);
    float cc = cosf(c), sc = sinf(c);
    float m00r = cb * ca, m00i = sb * sa;
    float m01r = -sb * ca, m01i = -cb * sa;
    float m10r = sb * ca, m10i = -cb * sa;
    float m11r = cb * ca, m11i = -sb * sa;
    float u00r = cc * m00r + sc * m00i, u00i = cc * m00i - sc * m00r;
    float u01r = cc * m01r + sc * m01i, u01i = cc * m01i - sc * m01r;
    float u10r = cc * m10r - sc * m10i, u10i = cc * m10i + sc * m10r;
    float u11r = cc * m11r - sc * m11i, u11i = cc * m11i + sc * m11r;
    float2* o = &g_gates2[g * 12];
    o[0]  = make_float2(u00r, u00r);
    o[1]  = make_float2(-u00i, -u00i);
    o[2]  = make_float2(u01r, u01r);
    o[3]  = make_float2(-u01i, -u01i);
    o[4]  = make_float2(u00i, u00i);
    o[5]  = make_float2(u01i, u01i);
    o[6]  = make_float2(u10r, u10r);
    o[7]  = make_float2(-u10i, -u10i);
    o[8]  = make_float2(u11r, u11r);
    o[9]  = make_float2(-u11i, -u11i);
    o[10] = make_float2(u10i, u10i);
    o[11] = make_float2(u11i, u11i);
}

// Apply the 3 gates whose qubit bits are the register-index bits (bit2,1,0 of r).
__device__ __forceinline__ void apply3(u64 vre[RPT], u64 vim[RPT],
                                       const u64* __restrict__ sG2, int gbase) {
#pragma unroll
    for (int qq = 0; qq < 3; qq++) {
        const u64* C = &sG2[(gbase + qq) * 12];
        const u64 c0 = C[0], c1 = C[1], c2 = C[2], c3 = C[3], c4 = C[4], c5 = C[5];
        const u64 c6 = C[6], c7 = C[7], c8 = C[8], c9 = C[9], c10 = C[10], c11 = C[11];
        const int mb = 4 >> qq;
#pragma unroll
        for (int r = 0; r < RPT; r++) {
            if (!(r & mb)) {
                const int r1 = r | mb;
                u64 a0re = vre[r],  a0im = vim[r];
                u64 a1re = vre[r1], a1im = vim[r1];
                u64 n0re = f2fma(c0, a0re, f2fma(c1, a0im, f2fma(c2, a1re, f2mul(c3, a1im))));
                u64 n0im = f2fma(c4, a0re, f2fma(c0, a0im, f2fma(c5, a1re, f2mul(c2, a1im))));
                u64 n1re = f2fma(c6, a0re, f2fma(c7, a0im, f2fma(c8, a1re, f2mul(c9, a1im))));
                u64 n1im = f2fma(c10, a0re, f2fma(c6, a0im, f2fma(c11, a1re, f2mul(c8, a1im))));
                vre[r] = n0re; vim[r] = n0im;
                vre[r1] = n1re; vim[r1] = n1im;
            }
        }
    }
}

// ---------------------------------------------------------------------------
// One CTA per BATCH PAIR (u64 packs elt0,elt1). 512 thr x 8 packed amps.
// (re,im) interleaved as ulonglong2 -> STS.128/LDS.128 exchanges (R14-proven).
// Layouts: L0 r={b11,b10,b9} | L1 r={b8,b7,b6} | L2 r={b5,b4,b3} | L3 r={b2,b1,b0}
// Sync scopes: X1 global | X2 64-grp bar64 | X3 in-warp | X4 (layers 0,1).
// Expectation tail (NEW): INVC bits only {11,2,1,0} and bit0-pattern == bit11-
// pattern, so acc_q = +/- one of 4 base sums {sum_all, S_b11, S_b2, S_b1},
// sign = thread's invt bit. ~160 fewer insts/thread than per-q signed adds.
// ---------------------------------------------------------------------------
extern __shared__ __align__(16) ulonglong2 dynsm2[];

__global__ __launch_bounds__(TPB, 1) void qsim_kernel(
    const float* __restrict__ x, float* __restrict__ out) {
    __shared__ u64 sG2[NGATES * 12];
    __shared__ u64 sRed[TPB / 32];
    __shared__ float sAcc[2 * NQ];

    ulonglong2* bA = dynsm2;
    ulonglong2* bB = dynsm2 + BUF;

    const int tid = threadIdx.x;
    const int bid = blockIdx.x;
    const float* xb0 = x + (size_t)(2 * bid) * DIM;
    const float* xb1 = xb0 + DIM;

    if (tid < NGATES * 12) sG2[tid] = ((const u64*)g_gates2)[tid];
    if (tid < 2 * NQ) sAcc[tid] = 0.0f;

    // ---- load both elements packed (L0) + per-element sum of squares ----
    u64 vre[RPT], vim[RPT];
    u64 ss = 0;
#pragma unroll
    for (int r = 0; r < RPT; r++) {
        int i = (r << 9) | tid;
        u64 v = pk2(xb0[i], xb1[i]);
        vre[r] = v;
        vim[r] = 0;
        ss = f2fma(v, v, ss);
    }
#pragma unroll
    for (int o = 16; o; o >>= 1) ss = f2add(ss, __shfl_xor_sync(0xffffffffu, ss, o));
    if ((tid & 31) == 0) sRed[tid >> 5] = ss;
    __syncthreads();
    ss = 0;
#pragma unroll
    for (int w = 0; w < TPB / 32; w++) ss = f2add(ss, sRed[w]);
    float s0, s1; unpk2(ss, s0, s1);
    const u64 inv = pk2(rsqrtf(s0), rsqrtf(s1));
#pragma unroll
    for (int r = 0; r < RPT; r++) vre[r] = f2mul(vre[r], inv);

    // exchange write bases (16-byte element units)
    const int base1 = (tid & 63) * STRIDE + ((tid >> 6) & 7);                      // +r*576
    const int base2 = (((tid >> 6) << 6) | (tid & 7)) * STRIDE + ((tid >> 3) & 7); // +r*72
    const int base3 = (tid >> 3) * (8 * STRIDE) + (tid & 7);                       // +r*9
    const int baseR = tid * STRIDE;                                                // canonical rows
    const int mybar = 1 + (tid >> 6);                                              // named barrier id 1..8
    // sigma(t): XOR-linear CNOT-ring permutation (verified)
    const int sig_t = ((tid ^ (tid >> 1)) & 0x0FF) | (tid & 0x100)
                    | ((tid & 1) ? 0xC00 : 0);
    // sigma^{-1}(tid<<3): reverse CNOT ring applied in forward order
    int invt = tid << 3;
#pragma unroll
    for (int g = 0; g < NQ; g++) {
        const int bc = 11 - g;
        const int bt = 11 - ((g + 1) % NQ);
        invt ^= ((invt >> bc) & 1) << bt;
    }

    // ---- circuit ----
#pragma unroll 1
    for (int layer = 0; layer < NLAYERS; layer++) {
        const int gbase = layer * NQ;

        apply3(vre, vim, sG2, gbase + 0);          // bits 11,10,9
#pragma unroll
        for (int r = 0; r < RPT; r++) {            // X1 write -> A (global shuffle)
            int a = base1 + r * (64 * STRIDE);
            bA[a] = make_ulonglong2(vre[r], vim[r]);
        }
        __syncthreads();
#pragma unroll
        for (int r = 0; r < RPT; r++) {
            ulonglong2 v = bA[baseR + r];
            vre[r] = v.x; vim[r] = v.y;
        }

        apply3(vre, vim, sG2, gbase + 3);          // bits 8,7,6
#pragma unroll
        for (int r = 0; r < RPT; r++) {            // X2 write -> B (64-thread groups)
            int a = base2 + r * (8 * STRIDE);
            bB[a] = make_ulonglong2(vre[r], vim[r]);
        }
        bar64(mybar);
#pragma unroll
        for (int r = 0; r < RPT; r++) {
            ulonglong2 v = bB[baseR + r];
            vre[r] = v.x; vim[r] = v.y;
        }

        apply3(vre, vim, sG2, gbase + 6);          // bits 5,4,3
#pragma unroll
        for (int r = 0; r < RPT; r++) {            // X3 write -> A (8-thread groups, in-warp)
            int a = base3 + r * STRIDE;
            bA[a] = make_ulonglong2(vre[r], vim[r]);
        }
        __syncwarp();
#pragma unroll
        for (int r = 0; r < RPT; r++) {
            ulonglong2 v = bA[baseR + r];
            vre[r] = v.x; vim[r] = v.y;
        }

        apply3(vre, vim, sG2, gbase + 9);          // bits 2,1,0
        if (layer < NLAYERS - 1) {
#pragma unroll
            for (int r = 0; r < RPT; r++) {        // X4 write -> B (own rows only)
                bB[baseR + r] = make_ulonglong2(vre[r], vim[r]);
            }
            __syncthreads();
            {
                // gather to L0 with CNOT-ring sigma folded in (verified constants)
                const int SIGC[RPT] = {0x000, 0x300, 0x600, 0x500,
                                       0xC00, 0xF00, 0xA00, 0x900};
#pragma unroll
                for (int r = 0; r < RPT; r++) {
                    int j = SIGC[r] ^ sig_t;
                    int a = j + (j >> 3);          // == (j>>3)*9 + (j&7)
                    ulonglong2 v = bB[a];
                    vre[r] = v.x; vim[r] = v.y;
                }
            }
        }
    }

    // ---- expectations via base sums ----
    // Final index of L3 amp j=(tid<<3)|r is i = invt ^ INVC[r], with
    // INVC = {0x000,0x801,0x803,0x002,0x807,0x006,0x004,0x805} (HW-validated).
    // INVC bits are only {11,2,1,0}; bit0 pattern == bit11 pattern.
    //   acc_q = (-1)^{invt_b} * S_b,  b = 11-q, where
    //   S_b = sum over r of (-1)^{INVC[r]_b} p[r]:
    //     b notin {11,2,1,0}: S_b = sum_all
    //     b=11 or b=0: signs - at r in {1,2,4,7}   (S11)
    //     b=2:        signs - at r in {4,5,6,7}    (S2)
    //     b=1:        signs - at r in {2,3,4,5}    (S1)
    const u64 SGN = 0x8000000080000000ULL;
    u64 p[RPT];
#pragma unroll
    for (int r = 0; r < RPT; r++)
        p[r] = f2fma(vre[r], vre[r], f2mul(vim[r], vim[r]));
    u64 e01 = f2add(p[0], p[1]), e23 = f2add(p[2], p[3]);
    u64 e45 = f2add(p[4], p[5]), e67 = f2add(p[6], p[7]);
    u64 d01 = f2add(p[0], p[1] ^ SGN), d23 = f2add(p[2], p[3] ^ SGN);
    u64 d45 = f2add(p[4], p[5] ^ SGN), d67 = f2add(p[6], p[7] ^ SGN);
    u64 t0 = f2add(e01, e23), t1 = f2add(e45, e67);
    u64 base[4];
    base[0] = f2add(t0, t1);                                    // sum_all
    base[1] = f2add(f2add(d01, d23 ^ SGN), f2add(d67, d45 ^ SGN)); // S11
    base[2] = f2add(t0, t1 ^ SGN);                              // S2
    base[3] = f2add(f2add(e01, e23 ^ SGN), f2add(e67, e45 ^ SGN)); // S1
    // qubit q uses invt bit (11-q); base index per q:
    const int BIDX[NQ] = {1, 0, 0, 0, 0, 0, 0, 0, 0, 2, 3, 1};
    u64 acc[NQ];
#pragma unroll
    for (int q = 0; q < NQ; q++) {
        u64 b = base[BIDX[q]];
        acc[q] = ((invt >> (11 - q)) & 1) ? (b ^ SGN) : b;
    }
#pragma unroll
    for (int q = 0; q < NQ; q++) {
#pragma unroll
        for (int o = 16; o; o >>= 1)
            acc[q] = f2add(acc[q], __shfl_xor_sync(0xffffffffu, acc[q], o));
    }
    if ((tid & 31) == 0) {
#pragma unroll
        for (int q = 0; q < NQ; q++) {
            float p0, p1; unpk2(acc[q], p0, p1);
            atomicAdd(&sAcc[q], p0);
            atomicAdd(&sAcc[NQ + q], p1);
        }
    }
    __syncthreads();
    if (tid < NQ) {
        out[(size_t)(2 * bid) * NQ + tid] = sAcc[tid];
        out[(size_t)(2 * bid + 1) * NQ + tid] = sAcc[NQ + tid];
    }
}

extern "C" void kernel_launch(void* const* d_in, const int* in_sizes, int n_in,
                              void* d_out, int out_size) {
    const float* x = (const float*)d_in[0];       // (8192, 4096) float32
    const float* params = (const float*)d_in[1];  // (108,) float32
    float* out = (float*)d_out;                   // (8192, 12) float32
    const int batch = in_sizes[0] / DIM;
    const int smem_bytes = 2 * BUF * (int)sizeof(ulonglong2); // 147456

    cudaFuncSetAttribute(qsim_kernel, cudaFuncAttributeMaxDynamicSharedMemorySize,
                         smem_bytes);
    prep_gates<<<1, 64>>>(params);
    qsim_kernel<<<batch / 2, TPB, smem_bytes>>>(x, out);
}

// round 16
// speedup vs baseline: 1.2410x; 1.0325x over previous
#include <cuda_runtime.h>

#define NQ 12
#define DIM 4096
#define NLAYERS 3
#define NGATES (NLAYERS * NQ)   // 36
#define TPB 512
#define RPT 8                   // register amplitudes per thread (per packed pair)
#define STRIDE 9                // padded smem row stride (in 16-byte units)
#define BUF (TPB * STRIDE)      // 4608 ulonglong2 (re,im pairs) per buffer
#define NSM 152                 // GB300 SM count (persistent grid)

typedef unsigned long long u64;

// Pre-packed gate coefficients: 36 gates x 12 float2 (duplicated / negated-duplicated)
__device__ float2 g_gates2[NGATES * 12];

// ---------------- f32x2 helpers (sm_103a packed fp32) ----------------
__device__ __forceinline__ u64 pk2(float x, float y) {
    u64 r; asm("mov.b64 %0, {%1, %2};" : "=l"(r) : "f"(x), "f"(y)); return r;
}
__device__ __forceinline__ void unpk2(u64 a, float& x, float& y) {
    asm("mov.b64 {%0, %1}, %2;" : "=f"(x), "=f"(y) : "l"(a));
}
__device__ __forceinline__ u64 f2fma(u64 a, u64 b, u64 c) {
    u64 d; asm("fma.rn.f32x2 %0, %1, %2, %3;" : "=l"(d) : "l"(a), "l"(b), "l"(c)); return d;
}
__device__ __forceinline__ u64 f2mul(u64 a, u64 b) {
    u64 d; asm("mul.rn.f32x2 %0, %1, %2;" : "=l"(d) : "l"(a), "l"(b)); return d;
}
__device__ __forceinline__ u64 f2add(u64 a, u64 b) {
    u64 d; asm("add.rn.f32x2 %0, %1, %2;" : "=l"(d) : "l"(a), "l"(b)); return d;
}
__device__ __forceinline__ void bar64(int id) {
    asm volatile("bar.sync %0, 64;" :: "r"(id) : "memory");
}

// ---------------------------------------------------------------------------
// Prep: fuse RZ*RY*RX per gate; emit 12 duplicated-packed coefficient pairs.
// ---------------------------------------------------------------------------
__global__ void prep_gates(const float* __restrict__ params) {
    int g = blockIdx.x * blockDim.x + threadIdx.x;
    if (g >= NGATES) return;
    float a = params[3 * g + 0] * 0.5f;
    float b = params[3 * g + 1] * 0.5f;
    float c = params[3 * g + 2] * 0.5f;
    float ca = cosf(a), sa = sinf(a);
    float cb = cosf(b), sb = sinf(b);
    float cc = cosf(c), sc = sinf(c);
    float m00r = cb * ca, m00i = sb * sa;
    float m01r = -sb * ca, m01i = -cb * sa;
    float m10r = sb * ca, m10i = -cb * sa;
    float m11r = cb * ca, m11i = -sb * sa;
    float u00r = cc * m00r + sc * m00i, u00i = cc * m00i - sc * m00r;
    float u01r = cc * m01r + sc * m01i, u01i = cc * m01i - sc * m01r;
    float u10r = cc * m10r - sc * m10i, u10i = cc * m10i + sc * m10r;
    float u11r = cc * m11r - sc * m11i, u11i = cc * m11i + sc * m11r;
    float2* o = &g_gates2[g * 12];
    o[0]  = make_float2(u00r, u00r);
    o[1]  = make_float2(-u00i, -u00i);
    o[2]  = make_float2(u01r, u01r);
    o[3]  = make_float2(-u01i, -u01i);
    o[4]  = make_float2(u00i, u00i);
    o[5]  = make_float2(u01i, u01i);
    o[6]  = make_float2(u10r, u10r);
    o[7]  = make_float2(-u10i, -u10i);
    o[8]  = make_float2(u11r, u11r);
    o[9]  = make_float2(-u11i, -u11i);
    o[10] = make_float2(u10i, u10i);
    o[11] = make_float2(u11i, u11i);
}

// Apply the 3 gates whose qubit bits are the register-index bits (bit2,1,0 of r).
__device__ __forceinline__ void apply3(u64 vre[RPT], u64 vim[RPT],
                                       const u64* __restrict__ sG2, int gbase) {
#pragma unroll
    for (int qq = 0; qq < 3; qq++) {
        const u64* C = &sG2[(gbase + qq) * 12];
        const u64 c0 = C[0], c1 = C[1], c2 = C[2], c3 = C[3], c4 = C[4], c5 = C[5];
        const u64 c6 = C[6], c7 = C[7], c8 = C[8], c9 = C[9], c10 = C[10], c11 = C[11];
        const int mb = 4 >> qq;
#pragma unroll
        for (int r = 0; r < RPT; r++) {
            if (!(r & mb)) {
                const int r1 = r | mb;
                u64 a0re = vre[r],  a0im = vim[r];
                u64 a1re = vre[r1], a1im = vim[r1];
                u64 n0re = f2fma(c0, a0re, f2fma(c1, a0im, f2fma(c2, a1re, f2mul(c3, a1im))));
                u64 n0im = f2fma(c4, a0re, f2fma(c0, a0im, f2fma(c5, a1re, f2mul(c2, a1im))));
                u64 n1re = f2fma(c6, a0re, f2fma(c7, a0im, f2fma(c8, a1re, f2mul(c9, a1im))));
                u64 n1im = f2fma(c10, a0re, f2fma(c6, a0im, f2fma(c11, a1re, f2mul(c8, a1im))));
                vre[r] = n0re; vim[r] = n0im;
                vre[r1] = n1re; vim[r1] = n1im;
            }
        }
    }
}

// ---------------------------------------------------------------------------
// PERSISTENT: grid = NSM CTAs; each loops over batch pairs with stride
// gridDim.x. Gate table + all index math hoisted out of the loop; no wave
// transitions. Per-pair body identical to the 499.8us kernel.
// ---------------------------------------------------------------------------
extern __shared__ __align__(16) ulonglong2 dynsm2[];

__global__ __launch_bounds__(TPB, 1) void qsim_kernel(
    const float* __restrict__ x, float* __restrict__ out, int npairs) {
    __shared__ u64 sG2[NGATES * 12];
    __shared__ u64 sRed[TPB / 32];
    __shared__ float sAcc[2 * NQ];

    ulonglong2* bA = dynsm2;
    ulonglong2* bB = dynsm2 + BUF;

    const int tid = threadIdx.x;

    if (tid < NGATES * 12) sG2[tid] = ((const u64*)g_gates2)[tid];

    // ---- loop-invariant exchange/index setup (hoisted) ----
    const int base1 = (tid & 63) * STRIDE + ((tid >> 6) & 7);                      // +r*576
    const int base2 = (((tid >> 6) << 6) | (tid & 7)) * STRIDE + ((tid >> 3) & 7); // +r*72
    const int base3 = (tid >> 3) * (8 * STRIDE) + (tid & 7);                       // +r*9
    const int baseR = tid * STRIDE;                                                // canonical rows
    const int mybar = 1 + (tid >> 6);                                              // named barrier id 1..8
    // sigma(t): XOR-linear CNOT-ring permutation (verified)
    const int sig_t = ((tid ^ (tid >> 1)) & 0x0FF) | (tid & 0x100)
                    | ((tid & 1) ? 0xC00 : 0);
    // sigma^{-1}(tid<<3): reverse CNOT ring applied in forward order
    int invt = tid << 3;
#pragma unroll
    for (int g = 0; g < NQ; g++) {
        const int bc = 11 - g;
        const int bt = 11 - ((g + 1) % NQ);
        invt ^= ((invt >> bc) & 1) << bt;
    }

    // ---- persistent loop over batch pairs ----
    for (int pid = blockIdx.x; pid < npairs; pid += gridDim.x) {
        const float* xb0 = x + (size_t)(2 * pid) * DIM;
        const float* xb1 = xb0 + DIM;

        if (tid < 2 * NQ) sAcc[tid] = 0.0f;

        // ---- load both elements packed (L0) + per-element sum of squares ----
        u64 vre[RPT], vim[RPT];
        u64 ss = 0;
#pragma unroll
        for (int r = 0; r < RPT; r++) {
            int i = (r << 9) | tid;
            u64 v = pk2(xb0[i], xb1[i]);
            vre[r] = v;
            vim[r] = 0;
            ss = f2fma(v, v, ss);
        }
#pragma unroll
        for (int o = 16; o; o >>= 1) ss = f2add(ss, __shfl_xor_sync(0xffffffffu, ss, o));
        if ((tid & 31) == 0) sRed[tid >> 5] = ss;
        __syncthreads();
        ss = 0;
#pragma unroll
        for (int w = 0; w < TPB / 32; w++) ss = f2add(ss, sRed[w]);
        float s0, s1; unpk2(ss, s0, s1);
        const u64 inv = pk2(rsqrtf(s0), rsqrtf(s1));
#pragma unroll
        for (int r = 0; r < RPT; r++) vre[r] = f2mul(vre[r], inv);

        // ---- circuit ----
#pragma unroll 1
        for (int layer = 0; layer < NLAYERS; layer++) {
            const int gbase = layer * NQ;

            apply3(vre, vim, sG2, gbase + 0);      // bits 11,10,9
#pragma unroll
            for (int r = 0; r < RPT; r++) {        // X1 write -> A (global shuffle)
                int a = base1 + r * (64 * STRIDE);
                bA[a] = make_ulonglong2(vre[r], vim[r]);
            }
            __syncthreads();
#pragma unroll
            for (int r = 0; r < RPT; r++) {
                ulonglong2 v = bA[baseR + r];
                vre[r] = v.x; vim[r] = v.y;
            }

            apply3(vre, vim, sG2, gbase + 3);      // bits 8,7,6
#pragma unroll
            for (int r = 0; r < RPT; r++) {        // X2 write -> B (64-thread groups)
                int a = base2 + r * (8 * STRIDE);
                bB[a] = make_ulonglong2(vre[r], vim[r]);
            }
            bar64(mybar);
#pragma unroll
            for (int r = 0; r < RPT; r++) {
                ulonglong2 v = bB[baseR + r];
                vre[r] = v.x; vim[r] = v.y;
            }

            apply3(vre, vim, sG2, gbase + 6);      // bits 5,4,3
#pragma unroll
            for (int r = 0; r < RPT; r++) {        // X3 write -> A (8-thread groups, in-warp)
                int a = base3 + r * STRIDE;
                bA[a] = make_ulonglong2(vre[r], vim[r]);
            }
            __syncwarp();
#pragma unroll
            for (int r = 0; r < RPT; r++) {
                ulonglong2 v = bA[baseR + r];
                vre[r] = v.x; vim[r] = v.y;
            }

            apply3(vre, vim, sG2, gbase + 9);      // bits 2,1,0
            if (layer < NLAYERS - 1) {
#pragma unroll
                for (int r = 0; r < RPT; r++) {    // X4 write -> B (own rows only)
                    bB[baseR + r] = make_ulonglong2(vre[r], vim[r]);
                }
                __syncthreads();
                {
                    // gather to L0 with CNOT-ring sigma folded in
                    const int SIGC[RPT] = {0x000, 0x300, 0x600, 0x500,
                                           0xC00, 0xF00, 0xA00, 0x900};
#pragma unroll
                    for (int r = 0; r < RPT; r++) {
                        int j = SIGC[r] ^ sig_t;
                        int a = j + (j >> 3);      // == (j>>3)*9 + (j&7)
                        ulonglong2 v = bB[a];
                        vre[r] = v.x; vim[r] = v.y;
                    }
                }
            }
        }

        // ---- expectations via base sums (sigma^{-1} fold; HW-validated) ----
        const u64 SGN = 0x8000000080000000ULL;
        u64 p[RPT];
#pragma unroll
        for (int r = 0; r < RPT; r++)
            p[r] = f2fma(vre[r], vre[r], f2mul(vim[r], vim[r]));
        u64 e01 = f2add(p[0], p[1]), e23 = f2add(p[2], p[3]);
        u64 e45 = f2add(p[4], p[5]), e67 = f2add(p[6], p[7]);
        u64 d01 = f2add(p[0], p[1] ^ SGN), d23 = f2add(p[2], p[3] ^ SGN);
        u64 d45 = f2add(p[4], p[5] ^ SGN), d67 = f2add(p[6], p[7] ^ SGN);
        u64 t0 = f2add(e01, e23), t1 = f2add(e45, e67);
        u64 base[4];
        base[0] = f2add(t0, t1);                                       // sum_all
        base[1] = f2add(f2add(d01, d23 ^ SGN), f2add(d67, d45 ^ SGN)); // S11
        base[2] = f2add(t0, t1 ^ SGN);                                 // S2
        base[3] = f2add(f2add(e01, e23 ^ SGN), f2add(e67, e45 ^ SGN)); // S1
        const int BIDX[NQ] = {1, 0, 0, 0, 0, 0, 0, 0, 0, 2, 3, 1};
        u64 acc[NQ];
#pragma unroll
        for (int q = 0; q < NQ; q++) {
            u64 b = base[BIDX[q]];
            acc[q] = ((invt >> (11 - q)) & 1) ? (b ^ SGN) : b;
        }
#pragma unroll
        for (int q = 0; q < NQ; q++) {
#pragma unroll
            for (int o = 16; o; o >>= 1)
                acc[q] = f2add(acc[q], __shfl_xor_sync(0xffffffffu, acc[q], o));
        }
        if ((tid & 31) == 0) {
#pragma unroll
            for (int q = 0; q < NQ; q++) {
                float p0, p1; unpk2(acc[q], p0, p1);
                atomicAdd(&sAcc[q], p0);
                atomicAdd(&sAcc[NQ + q], p1);
            }
        }
        __syncthreads();
        if (tid < NQ) {
            out[(size_t)(2 * pid) * NQ + tid] = sAcc[tid];
            out[(size_t)(2 * pid + 1) * NQ + tid] = sAcc[NQ + tid];
        }
        __syncthreads();   // sAcc readers done before next iteration's zeroing
    }
}

extern "C" void kernel_launch(void* const* d_in, const int* in_sizes, int n_in,
                              void* d_out, int out_size) {
    const float* x = (const float*)d_in[0];       // (8192, 4096) float32
    const float* params = (const float*)d_in[1];  // (108,) float32
    float* out = (float*)d_out;                   // (8192, 12) float32
    const int npairs = (in_sizes[0] / DIM) / 2;   // 4096
    const int smem_bytes = 2 * BUF * (int)sizeof(ulonglong2); // 147456
    const int grid = npairs < NSM ? npairs : NSM;

    cudaFuncSetAttribute(qsim_kernel, cudaFuncAttributeMaxDynamicSharedMemorySize,
                         smem_bytes);
    prep_gates<<<1, 64>>>(params);
    qsim_kernel<<<grid, TPB, smem_bytes>>>(x, out, npairs);
}

// round 17
// speedup vs baseline: 1.2971x; 1.0453x over previous
#include <cuda_runtime.h>

#define NQ 12
#define DIM 4096
#define NLAYERS 3
#define NGATES (NLAYERS * NQ)   // 36
#define GC 8                    // coefficients per gate (7 unique + pad)
#define TPB 512
#define RPT 8                   // register amplitudes per thread (per packed pair)
#define STRIDE 9                // padded smem row stride (in 16-byte units)
#define BUF (TPB * STRIDE)      // 4608 ulonglong2 (re,im pairs) per buffer
#define NSM 152                 // GB300 SM count (persistent grid)

typedef unsigned long long u64;

// Pre-packed gate coefficients: 36 gates x 8 float2 (SU(2)-reduced set)
__device__ float2 g_gates2[NGATES * GC];

// ---------------- f32x2 helpers (sm_103a packed fp32) ----------------
__device__ __forceinline__ u64 pk2(float x, float y) {
    u64 r; asm("mov.b64 %0, {%1, %2};" : "=l"(r) : "f"(x), "f"(y)); return r;
}
__device__ __forceinline__ void unpk2(u64 a, float& x, float& y) {
    asm("mov.b64 {%0, %1}, %2;" : "=f"(x), "=f"(y) : "l"(a));
}
__device__ __forceinline__ u64 f2fma(u64 a, u64 b, u64 c) {
    u64 d; asm("fma.rn.f32x2 %0, %1, %2, %3;" : "=l"(d) : "l"(a), "l"(b), "l"(c)); return d;
}
__device__ __forceinline__ u64 f2mul(u64 a, u64 b) {
    u64 d; asm("mul.rn.f32x2 %0, %1, %2;" : "=l"(d) : "l"(a), "l"(b)); return d;
}
__device__ __forceinline__ u64 f2add(u64 a, u64 b) {
    u64 d; asm("add.rn.f32x2 %0, %1, %2;" : "=l"(d) : "l"(a), "l"(b)); return d;
}
__device__ __forceinline__ void bar64(int id) {
    asm volatile("bar.sync %0, 64;" :: "r"(id) : "memory");
}

// ---------------------------------------------------------------------------
// Prep: fuse RZ*RY*RX per gate. SU(2) structure: U = [[a, -conj(b)],[b, conj(a)]]
// with u00=alpha, u01=-conj(beta). Emit 7 unique duplicated-packed coeffs:
//   c0=u00r c1=-u00i c2=u01r c3=-u01i c4=u00i c5=u01i c6=-u01r (c7 pad)
// ---------------------------------------------------------------------------
__global__ void prep_gates(const float* __restrict__ params) {
    int g = blockIdx.x * blockDim.x + threadIdx.x;
    if (g >= NGATES) return;
    float a = params[3 * g + 0] * 0.5f;
    float b = params[3 * g + 1] * 0.5f;
    float c = params[3 * g + 2] * 0.5f;
    float ca = cosf(a), sa = sinf(a);
    float cb = cosf(b), sb = sinf(b);
    float cc = cosf(c), sc = sinf(c);
    float m00r = cb * ca, m00i = sb * sa;
    float m01r = -sb * ca, m01i = -cb * sa;
    float u00r = cc * m00r + sc * m00i, u00i = cc * m00i - sc * m00r;
    float u01r = cc * m01r + sc * m01i, u01i = cc * m01i - sc * m01r;
    float2* o = &g_gates2[g * GC];
    o[0] = make_float2(u00r, u00r);
    o[1] = make_float2(-u00i, -u00i);
    o[2] = make_float2(u01r, u01r);
    o[3] = make_float2(-u01i, -u01i);
    o[4] = make_float2(u00i, u00i);
    o[5] = make_float2(u01i, u01i);
    o[6] = make_float2(-u01r, -u01r);
    o[7] = make_float2(0.0f, 0.0f);
}

// Apply the 3 gates whose qubit bits are the register-index bits (bit2,1,0 of r).
// Coefficients loaded as 4x LDS.128 (broadcast, conflict-free).
// Chains (verified against complex matvec with u10=-conj(u01), u11=conj(u00)):
//   n0re = c0 a0re + c1 a0im + c2 a1re + c3 a1im
//   n0im = c4 a0re + c0 a0im + c5 a1re + c2 a1im
//   n1re = c6 a0re + c3 a0im + c0 a1re + c4 a1im
//   n1im = c5 a0re + c6 a0im + c1 a1re + c0 a1im
__device__ __forceinline__ void apply3(u64 vre[RPT], u64 vim[RPT],
                                       const u64* __restrict__ sG2, int gbase) {
#pragma unroll
    for (int qq = 0; qq < 3; qq++) {
        const ulonglong2* C2 =
            reinterpret_cast<const ulonglong2*>(&sG2[(gbase + qq) * GC]);
        const ulonglong2 p01 = C2[0], p23 = C2[1], p45 = C2[2], p6x = C2[3];
        const u64 c0 = p01.x, c1 = p01.y, c2 = p23.x, c3 = p23.y;
        const u64 c4 = p45.x, c5 = p45.y, c6 = p6x.x;
        const int mb = 4 >> qq;
#pragma unroll
        for (int r = 0; r < RPT; r++) {
            if (!(r & mb)) {
                const int r1 = r | mb;
                u64 a0re = vre[r],  a0im = vim[r];
                u64 a1re = vre[r1], a1im = vim[r1];
                u64 n0re = f2fma(c0, a0re, f2fma(c1, a0im, f2fma(c2, a1re, f2mul(c3, a1im))));
                u64 n0im = f2fma(c4, a0re, f2fma(c0, a0im, f2fma(c5, a1re, f2mul(c2, a1im))));
                u64 n1re = f2fma(c6, a0re, f2fma(c3, a0im, f2fma(c0, a1re, f2mul(c4, a1im))));
                u64 n1im = f2fma(c5, a0re, f2fma(c6, a0im, f2fma(c1, a1re, f2mul(c0, a1im))));
                vre[r] = n0re; vim[r] = n0im;
                vre[r1] = n1re; vim[r1] = n1im;
            }
        }
    }
}

// ---------------------------------------------------------------------------
// PERSISTENT: grid = NSM CTAs striding over batch pairs. Normalization is
// DEFERRED: circuit is linear, so probabilities are scaled by 1/||x||^2 at
// the tail (per-warp partial sums written to sRed at load; ordered by the
// layer-0 X1 barrier; read at tail; next-iter overwrite ordered by the final
// barrier). Saves one full __syncthreads per pair.
// ---------------------------------------------------------------------------
extern __shared__ __align__(16) ulonglong2 dynsm2[];

__global__ __launch_bounds__(TPB, 1) void qsim_kernel(
    const float* __restrict__ x, float* __restrict__ out, int npairs) {
    __shared__ u64 sG2[NGATES * GC];
    __shared__ u64 sRed[TPB / 32];
    __shared__ float sAcc[2 * NQ];

    ulonglong2* bA = dynsm2;
    ulonglong2* bB = dynsm2 + BUF;

    const int tid = threadIdx.x;

    if (tid < NGATES * GC) sG2[tid] = ((const u64*)g_gates2)[tid];

    // ---- loop-invariant exchange/index setup (hoisted) ----
    const int base1 = (tid & 63) * STRIDE + ((tid >> 6) & 7);                      // +r*576
    const int base2 = (((tid >> 6) << 6) | (tid & 7)) * STRIDE + ((tid >> 3) & 7); // +r*72
    const int base3 = (tid >> 3) * (8 * STRIDE) + (tid & 7);                       // +r*9
    const int baseR = tid * STRIDE;                                                // canonical rows
    const int mybar = 1 + (tid >> 6);                                              // named barrier id 1..8
    // sigma(t): XOR-linear CNOT-ring permutation (verified)
    const int sig_t = ((tid ^ (tid >> 1)) & 0x0FF) | (tid & 0x100)
                    | ((tid & 1) ? 0xC00 : 0);
    // sigma^{-1}(tid<<3): reverse CNOT ring applied in forward order
    int invt = tid << 3;
#pragma unroll
    for (int g = 0; g < NQ; g++) {
        const int bc = 11 - g;
        const int bt = 11 - ((g + 1) % NQ);
        invt ^= ((invt >> bc) & 1) << bt;
    }

    // ---- persistent loop over batch pairs ----
    for (int pid = blockIdx.x; pid < npairs; pid += gridDim.x) {
        const float* xb0 = x + (size_t)(2 * pid) * DIM;
        const float* xb1 = xb0 + DIM;

        if (tid < 2 * NQ) sAcc[tid] = 0.0f;

        // ---- load both elements packed (L0); per-warp sum-of-squares -> sRed ----
        u64 vre[RPT], vim[RPT];
        u64 ss = 0;
#pragma unroll
        for (int r = 0; r < RPT; r++) {
            int i = (r << 9) | tid;
            u64 v = pk2(xb0[i], xb1[i]);
            vre[r] = v;
            vim[r] = 0;
            ss = f2fma(v, v, ss);
        }
#pragma unroll
        for (int o = 16; o; o >>= 1) ss = f2add(ss, __shfl_xor_sync(0xffffffffu, ss, o));
        if ((tid & 31) == 0) sRed[tid >> 5] = ss;
        // no barrier: the layer-0 X1 __syncthreads orders sRed for tail readers

        // ---- circuit (on unnormalized amplitudes) ----
#pragma unroll 1
        for (int layer = 0; layer < NLAYERS; layer++) {
            const int gbase = layer * NQ;

            apply3(vre, vim, sG2, gbase + 0);      // bits 11,10,9
#pragma unroll
            for (int r = 0; r < RPT; r++) {        // X1 write -> A (global shuffle)
                int a = base1 + r * (64 * STRIDE);
                bA[a] = make_ulonglong2(vre[r], vim[r]);
            }
            __syncthreads();
#pragma unroll
            for (int r = 0; r < RPT; r++) {
                ulonglong2 v = bA[baseR + r];
                vre[r] = v.x; vim[r] = v.y;
            }

            apply3(vre, vim, sG2, gbase + 3);      // bits 8,7,6
#pragma unroll
            for (int r = 0; r < RPT; r++) {        // X2 write -> B (64-thread groups)
                int a = base2 + r * (8 * STRIDE);
                bB[a] = make_ulonglong2(vre[r], vim[r]);
            }
            bar64(mybar);
#pragma unroll
            for (int r = 0; r < RPT; r++) {
                ulonglong2 v = bB[baseR + r];
                vre[r] = v.x; vim[r] = v.y;
            }

            apply3(vre, vim, sG2, gbase + 6);      // bits 5,4,3
#pragma unroll
            for (int r = 0; r < RPT; r++) {        // X3 write -> A (8-thread groups, in-warp)
                int a = base3 + r * STRIDE;
                bA[a] = make_ulonglong2(vre[r], vim[r]);
            }
            __syncwarp();
#pragma unroll
            for (int r = 0; r < RPT; r++) {
                ulonglong2 v = bA[baseR + r];
                vre[r] = v.x; vim[r] = v.y;
            }

            apply3(vre, vim, sG2, gbase + 9);      // bits 2,1,0
            if (layer < NLAYERS - 1) {
#pragma unroll
                for (int r = 0; r < RPT; r++) {    // X4 write -> B (own rows only)
                    bB[baseR + r] = make_ulonglong2(vre[r], vim[r]);
                }
                __syncthreads();
                {
                    // gather to L0 with CNOT-ring sigma folded in
                    const int SIGC[RPT] = {0x000, 0x300, 0x600, 0x500,
                                           0xC00, 0xF00, 0xA00, 0x900};
#pragma unroll
                    for (int r = 0; r < RPT; r++) {
                        int j = SIGC[r] ^ sig_t;
                        int a = j + (j >> 3);      // == (j>>3)*9 + (j&7)
                        ulonglong2 v = bB[a];
                        vre[r] = v.x; vim[r] = v.y;
                    }
                }
            }
        }

        // ---- norm factor (deferred): 1/||x||^2 per element ----
        u64 nrm = 0;
#pragma unroll
        for (int w = 0; w < TPB / 32; w++) nrm = f2add(nrm, sRed[w]);
        float s0, s1; unpk2(nrm, s0, s1);
        float r0 = rsqrtf(s0), r1 = rsqrtf(s1);
        const u64 inv2 = pk2(r0 * r0, r1 * r1);

        // ---- expectations via base sums (sigma^{-1} fold; HW-validated) ----
        const u64 SGN = 0x8000000080000000ULL;
        u64 p[RPT];
#pragma unroll
        for (int r = 0; r < RPT; r++)
            p[r] = f2fma(vre[r], vre[r], f2mul(vim[r], vim[r]));
        u64 e01 = f2add(p[0], p[1]), e23 = f2add(p[2], p[3]);
        u64 e45 = f2add(p[4], p[5]), e67 = f2add(p[6], p[7]);
        u64 d01 = f2add(p[0], p[1] ^ SGN), d23 = f2add(p[2], p[3] ^ SGN);
        u64 d45 = f2add(p[4], p[5] ^ SGN), d67 = f2add(p[6], p[7] ^ SGN);
        u64 t0 = f2add(e01, e23), t1 = f2add(e45, e67);
        u64 base[4];
        base[0] = f2mul(f2add(t0, t1), inv2);                                       // sum_all
        base[1] = f2mul(f2add(f2add(d01, d23 ^ SGN), f2add(d67, d45 ^ SGN)), inv2); // S11
        base[2] = f2mul(f2add(t0, t1 ^ SGN), inv2);                                 // S2
        base[3] = f2mul(f2add(f2add(e01, e23 ^ SGN), f2add(e67, e45 ^ SGN)), inv2); // S1
        const int BIDX[NQ] = {1, 0, 0, 0, 0, 0, 0, 0, 0, 2, 3, 1};
        u64 acc[NQ];
#pragma unroll
        for (int q = 0; q < NQ; q++) {
            u64 b = base[BIDX[q]];
            acc[q] = ((invt >> (11 - q)) & 1) ? (b ^ SGN) : b;
        }
#pragma unroll
        for (int q = 0; q < NQ; q++) {
#pragma unroll
            for (int o = 16; o; o >>= 1)
                acc[q] = f2add(acc[q], __shfl_xor_sync(0xffffffffu, acc[q], o));
        }
        if ((tid & 31) == 0) {
#pragma unroll
            for (int q = 0; q < NQ; q++) {
                float p0, p1; unpk2(acc[q], p0, p1);
                atomicAdd(&sAcc[q], p0);
                atomicAdd(&sAcc[NQ + q], p1);
            }
        }
        __syncthreads();
        if (tid < NQ) {
            out[(size_t)(2 * pid) * NQ + tid] = sAcc[tid];
            out[(size_t)(2 * pid + 1) * NQ + tid] = sAcc[NQ + tid];
        }
        __syncthreads();   // sAcc/sRed readers done before next iteration
    }
}

extern "C" void kernel_launch(void* const* d_in, const int* in_sizes, int n_in,
                              void* d_out, int out_size) {
    const float* x = (const float*)d_in[0];       // (8192, 4096) float32
    const float* params = (const float*)d_in[1];  // (108,) float32
    float* out = (float*)d_out;                   // (8192, 12) float32
    const int npairs = (in_sizes[0] / DIM) / 2;   // 4096
    const int smem_bytes = 2 * BUF * (int)sizeof(ulonglong2); // 147456
    const int grid = npairs < NSM ? npairs : NSM;

    cudaFuncSetAttribute(qsim_kernel, cudaFuncAttributeMaxDynamicSharedMemorySize,
                         smem_bytes);
    prep_gates<<<1, 64>>>(params);
    qsim_kernel<<<grid, TPB, smem_bytes>>>(x, out, npairs);
}